// round 1
// baseline (speedup 1.0000x reference)
#include <cuda_runtime.h>
#include <cuda_bf16.h>
#include <math.h>

#define Nn 1024
#define Qq 32
#define Mm 256
#define Dd 32
#define JITTER 1e-6f

// ---------------- scratch (device globals; no allocation) ----------------
__device__ float g_w1[Nn*Qq];
__device__ float g_w2[Nn*Qq];
__device__ float g_e1[Nn];
__device__ float g_e2[Nn];
__device__ float g_qmk[Mm*Mm];
__device__ float g_Kmm[Mm*Mm];
__device__ float g_L[Mm*Mm];
__device__ float g_Linv[Mm*Mm];
__device__ float g_Kinv[Mm*Mm];
__device__ float g_psi1[Nn*Mm];
__device__ float g_psi2[Mm*Mm];
__device__ float g_A1[Nn*Mm];
__device__ float g_R[Mm*Mm*Dd];      // 8 MB  masked q_sqrt
__device__ float g_uuT[Mm*Mm];
__device__ float g_P2[Mm*Mm];
__device__ float g_KPK[Mm*Mm];
__device__ float g_G[Mm*Mm];
__device__ float g_tmpF[(size_t)Nn*Mm*Dd]; // 32 MB

// ---------------- per-n prep: w1,w2,logdet terms ----------------
__global__ void prep_n_kernel(const float* __restrict__ Xvar,
                              const float* __restrict__ ls)
{
    int n = blockIdx.x*blockDim.x + threadIdx.x;
    if (n >= Nn) return;
    float ld1 = 0.f, ld2 = 0.f;
    #pragma unroll
    for (int q = 0; q < Qq; q++){
        float l = ls[q];
        float l2 = l*l;
        float S = Xvar[n*Qq+q];
        float d1 = l2 + S;
        float d2 = l2 + 2.f*S;
        g_w1[n*Qq+q] = 1.f/d1;
        g_w2[n*Qq+q] = 1.f/d2;
        ld1 += logf(d1/l2);
        ld2 += logf(d2/l2);
    }
    g_e1[n] = -0.5f*ld1;
    g_e2[n] = -0.5f*ld2;
}

// ---------------- qmk and Kmm ----------------
__global__ void prep_kmm_kernel(const float* __restrict__ Z,
                                const float* __restrict__ ls,
                                const float* __restrict__ var_p)
{
    int idx = blockIdx.x*blockDim.x + threadIdx.x;
    if (idx >= Mm*Mm) return;
    int m = idx / Mm, k = idx % Mm;
    float s = 0.f;
    #pragma unroll
    for (int q = 0; q < Qq; q++){
        float l = ls[q];
        float d = Z[m*Qq+q] - Z[k*Qq+q];
        s += (d*d)/(l*l);
    }
    g_qmk[idx] = s;
    float v = var_p[0];
    g_Kmm[idx] = v*expf(-0.5f*s) + ((m==k)?JITTER:0.f);
}

// ---------------- psi1 ----------------
__global__ void psi1_kernel(const float* __restrict__ Z,
                            const float* __restrict__ Xmean,
                            const float* __restrict__ var_p)
{
    int tx = threadIdx.x, ty = threadIdx.y;
    int m = blockIdx.x*32 + tx;
    int n0 = blockIdx.y*8;
    int n = n0 + ty;
    __shared__ float Zs[32][33];
    __shared__ float ws[8][32], ms[8][32], es[8];
    int t = ty*32 + tx;
    for (int i = t; i < 32*Qq; i += 256){
        int r = i/Qq, q = i%Qq;
        Zs[r][q] = Z[(blockIdx.x*32+r)*Qq + q];
    }
    for (int i = t; i < 8*Qq; i += 256){
        int r = i/Qq, q = i%Qq;
        ws[r][q] = g_w1[(n0+r)*Qq + q];
        ms[r][q] = Xmean[(n0+r)*Qq + q];
    }
    if (t < 8) es[t] = g_e1[n0+t];
    __syncthreads();
    float s = 0.f;
    #pragma unroll
    for (int q = 0; q < Qq; q++){
        float d = ms[ty][q] - Zs[tx][q];
        s = fmaf(ws[ty][q], d*d, s);
    }
    g_psi1[n*Mm + m] = var_p[0]*expf(es[ty] - 0.5f*s);
}

// ---------------- psi2 (upper tile-triangle only) ----------------
__global__ void psi2_kernel(const float* __restrict__ Z,
                            const float* __restrict__ var_p)
{
    // decode (bi<=bj) tile pair from linear index (16x16 tiles -> 136 pairs)
    int rem = blockIdx.x, bi = 0;
    for (bi = 0; bi < 16; bi++){ int len = 16-bi; if (rem < len) break; rem -= len; }
    int bj = bi + rem;
    int tx = threadIdx.x, ty = threadIdx.y;
    int m = bi*16 + ty;
    int k = bj*16 + tx;
    int t = ty*16 + tx;

    __shared__ float Zm[16][33], Zk[16][33];
    for (int i = t; i < 16*Qq; i += 256){
        int r = i/Qq, q = i%Qq;
        Zm[r][q] = Z[(bi*16+r)*Qq + q];
        Zk[r][q] = Z[(bj*16+r)*Qq + q];
    }
    __syncthreads();
    float zbar[Qq];
    #pragma unroll
    for (int q = 0; q < Qq; q++) zbar[q] = 0.5f*(Zm[ty][q] + Zk[tx][q]);
    float base = -0.25f*g_qmk[m*Mm + k];

    __shared__ float wb[16][33], mb[16][33], eb[16];
    float acc = 0.f;
    for (int n0 = 0; n0 < Nn; n0 += 16){
        __syncthreads();
        for (int i = t; i < 16*Qq; i += 256){
            int r = i/Qq, q = i%Qq;
            wb[r][q] = g_w2[(n0+r)*Qq + q];
            mb[r][q] = zbar[0]*0.f + 0.f; // placeholder overwritten below
        }
        // separate pass (avoid compiler folding): load mean
        for (int i = t; i < 16*Qq; i += 256){
            int r = i/Qq, q = i%Qq;
            mb[r][q] = g_w2[0]*0.f + 0.f;
        }
        // NOTE: actual loads below
        for (int i = t; i < 16*Qq; i += 256){
            int r = i/Qq, q = i%Qq;
            mb[r][q] = 0.f;
        }
        if (t < 16) eb[t] = g_e2[n0+t];
        __syncthreads();
        // real mean load happens via global pointer passed at launch (see psi2_mu)
        // -- replaced: see psi2_kernel2 below --
        (void)acc;
        break;
    }
    // This kernel body is replaced by psi2_kernel2; kept minimal to avoid use.
    if (blockIdx.x == 0xFFFFFFFF) g_psi2[0] = acc; // never
}

// real psi2 kernel (clean version)
__global__ void psi2_kernel2(const float* __restrict__ Z,
                             const float* __restrict__ Xmean,
                             const float* __restrict__ var_p)
{
    int rem = blockIdx.x, bi = 0;
    for (bi = 0; bi < 16; bi++){ int len = 16-bi; if (rem < len) break; rem -= len; }
    int bj = bi + rem;
    int tx = threadIdx.x, ty = threadIdx.y;
    int m = bi*16 + ty;
    int k = bj*16 + tx;
    int t = ty*16 + tx;

    __shared__ float Zm[16][33], Zk[16][33];
    for (int i = t; i < 16*Qq; i += 256){
        int r = i/Qq, q = i%Qq;
        Zm[r][q] = Z[(bi*16+r)*Qq + q];
        Zk[r][q] = Z[(bj*16+r)*Qq + q];
    }
    __syncthreads();
    float zbar[Qq];
    #pragma unroll
    for (int q = 0; q < Qq; q++) zbar[q] = 0.5f*(Zm[ty][q] + Zk[tx][q]);
    float base = -0.25f*g_qmk[m*Mm + k];

    __shared__ float wb[16][33], mb[16][33], eb[16];
    float acc = 0.f;
    for (int n0 = 0; n0 < Nn; n0 += 16){
        __syncthreads();
        for (int i = t; i < 16*Qq; i += 256){
            int r = i/Qq, q = i%Qq;
            wb[r][q] = g_w2[(n0+r)*Qq + q];
            mb[r][q] = Xmean[(n0+r)*Qq + q];
        }
        if (t < 16) eb[t] = g_e2[n0+t];
        __syncthreads();
        #pragma unroll 2
        for (int nn = 0; nn < 16; nn++){
            float r = 0.f;
            #pragma unroll
            for (int q = 0; q < Qq; q++){
                float d = mb[nn][q] - zbar[q];
                r = fmaf(wb[nn][q], d*d, r);
            }
            acc += __expf(base + eb[nn] - r);
        }
    }
    float v = var_p[0];
    g_psi2[m*Mm + k] = v*v*acc;
}

__global__ void psi2_mirror_kernel()
{
    int idx = blockIdx.x*blockDim.x + threadIdx.x;
    if (idx >= Mm*Mm) return;
    int m = idx / Mm, k = idx % Mm;
    if ((m>>4) > (k>>4)) g_psi2[m*Mm+k] = g_psi2[k*Mm+m];
}

// ---------------- Cholesky of Kmm (single block) ----------------
__global__ void cholesky_kernel()
{
    int t = threadIdx.x;
    for (int i = t; i < Mm*Mm; i += 256) g_L[i] = g_Kmm[i];
    __syncthreads();
    __shared__ float colk[Mm];
    for (int k = 0; k < Mm; k++){
        if (t == 0) g_L[k*Mm+k] = sqrtf(g_L[k*Mm+k]);
        __syncthreads();
        float Lkk = g_L[k*Mm+k];
        float v = 0.f;
        if (t > k){ v = g_L[t*Mm+k]/Lkk; g_L[t*Mm+k] = v; }
        colk[t] = v;
        __syncthreads();
        int rl = t>>3, cl = t&7;
        for (int i = k+1+rl; i < Mm; i += 32){
            float ci = colk[i];
            for (int j = k+1+cl; j <= i; j += 8)
                g_L[i*Mm+j] -= ci*colk[j];
        }
        __syncthreads();
    }
    for (int i = t; i < Mm*Mm; i += 256){
        int r = i/Mm, c = i%Mm;
        if (c > r) g_L[i] = 0.f;
    }
}

// ---------------- Linv = L^{-1} via forward substitution on identity ----------------
__global__ void trisolve_kernel()
{
    int c0 = blockIdx.x*32;
    int t = threadIdx.x;
    __shared__ float X[Mm][32];
    for (int i = t; i < Mm*32; i += 256){
        int r = i/32, c = i%32;
        X[r][c] = (r == c0+c) ? 1.f : 0.f;
    }
    __syncthreads();
    int c = t&31, ro = t>>5;
    for (int j = c0; j < Mm; j++){
        if (t < 32) X[j][t] = X[j][t]/g_L[j*Mm+j];
        __syncthreads();
        float xjc = X[j][c];
        for (int i = j+1+ro; i < Mm; i += 8)
            X[i][c] -= g_L[i*Mm+j]*xjc;
        __syncthreads();
    }
    for (int i = t; i < Mm*32; i += 256){
        int r = i/32, cc = i%32;
        g_Linv[r*Mm + c0 + cc] = X[r][cc];
    }
}

// ---------------- masked R from q_sqrt ----------------
__global__ void maskR_kernel(const float* __restrict__ qs)
{
    int idx = blockIdx.x*blockDim.x + threadIdx.x;
    if (idx >= Mm*Mm*Dd) return;
    int a = idx / (Mm*Dd);
    int b = (idx / Dd) % Mm;
    g_R[idx] = (b <= a) ? qs[idx] : 0.f;
}

// ---------------- generic SGEMM: C = alpha*op(A)op(B) + beta*C ----------------
template<int TA, int TB>
__global__ void sgemm(int M_, int N_, int K_,
                      const float* __restrict__ A, int lda,
                      const float* __restrict__ B, int ldb,
                      float* __restrict__ C, int ldc,
                      float alpha, float beta)
{
    const int BM = 64, BN = 64, BK = 16;
    __shared__ float As[BK][BM+1];
    __shared__ float Bs[BK][BN+1];
    int bm = blockIdx.y*BM, bn = blockIdx.x*BN;
    int tid = threadIdx.x;
    int tm = (tid/16)*4, tn = (tid%16)*4;
    float acc[4][4] = {};
    for (int k0 = 0; k0 < K_; k0 += BK){
        if (!TA){
            for (int i = tid; i < BM*BK; i += 256){
                int kk = i%BK, mm = i/BK;
                int gm = bm+mm, gk = k0+kk;
                As[kk][mm] = (gm < M_ && gk < K_) ? A[(size_t)gm*lda + gk] : 0.f;
            }
        } else {
            for (int i = tid; i < BM*BK; i += 256){
                int mm = i%BM, kk = i/BM;
                int gm = bm+mm, gk = k0+kk;
                As[kk][mm] = (gm < M_ && gk < K_) ? A[(size_t)gk*lda + gm] : 0.f;
            }
        }
        if (!TB){
            for (int i = tid; i < BN*BK; i += 256){
                int nn = i%BN, kk = i/BN;
                int gn = bn+nn, gk = k0+kk;
                Bs[kk][nn] = (gn < N_ && gk < K_) ? B[(size_t)gk*ldb + gn] : 0.f;
            }
        } else {
            for (int i = tid; i < BN*BK; i += 256){
                int kk = i%BK, nn = i/BK;
                int gn = bn+nn, gk = k0+kk;
                Bs[kk][nn] = (gn < N_ && gk < K_) ? B[(size_t)gn*ldb + gk] : 0.f;
            }
        }
        __syncthreads();
        #pragma unroll
        for (int kk = 0; kk < BK; kk++){
            float ra[4], rb[4];
            #pragma unroll
            for (int i = 0; i < 4; i++){ ra[i] = As[kk][tm+i]; rb[i] = Bs[kk][tn+i]; }
            #pragma unroll
            for (int i = 0; i < 4; i++)
                #pragma unroll
                for (int j = 0; j < 4; j++)
                    acc[i][j] = fmaf(ra[i], rb[j], acc[i][j]);
        }
        __syncthreads();
    }
    #pragma unroll
    for (int i = 0; i < 4; i++){
        int gm = bm + tm + i;
        if (gm >= M_) continue;
        #pragma unroll
        for (int j = 0; j < 4; j++){
            int gn = bn + tn + j;
            if (gn >= N_) continue;
            float prev = (beta != 0.f) ? C[(size_t)gm*ldc + gn] : 0.f;
            C[(size_t)gm*ldc + gn] = alpha*acc[i][j] + beta*prev;
        }
    }
}

// ---------------- batched SYRK for forward_var ----------------
__global__ void var_kernel(float* __restrict__ out_var, const float* __restrict__ beta_p)
{
    __shared__ float T[Mm*Dd]; // 32 KB
    int n = blockIdx.x;
    int t = threadIdx.x;
    for (int i = t; i < Mm*Dd; i += 256) T[i] = g_tmpF[(size_t)n*(Mm*Dd) + i];
    __syncthreads();
    float invb = 1.f/beta_p[0];
    int e = t & 31, d0 = (t >> 5)*4;
    float a0=0.f, a1=0.f, a2=0.f, a3=0.f;
    for (int m = 0; m < Mm; m++){
        float te = T[m*32 + e];
        a0 = fmaf(T[m*32 + d0+0], te, a0);
        a1 = fmaf(T[m*32 + d0+1], te, a1);
        a2 = fmaf(T[m*32 + d0+2], te, a2);
        a3 = fmaf(T[m*32 + d0+3], te, a3);
    }
    float* vp = out_var + (size_t)n*Dd*Dd;
    vp[(d0+0)*32 + e] = a0 + ((d0+0)==e ? invb : 0.f);
    vp[(d0+1)*32 + e] = a1 + ((d0+1)==e ? invb : 0.f);
    vp[(d0+2)*32 + e] = a2 + ((d0+2)==e ? invb : 0.f);
    vp[(d0+3)*32 + e] = a3 + ((d0+3)==e ? invb : 0.f);
}

// ---------------- final scalar reduction -> lml ----------------
__global__ void reduce_lml_kernel(float* __restrict__ out_lml,
                                  const float* __restrict__ var_p,
                                  const float* __restrict__ beta_p,
                                  const float* __restrict__ qs)
{
    __shared__ double red[256];
    int t = threadIdx.x;
    double a1=0, a2=0, a3=0, a4=0, a5=0, a6=0;
    for (int i = t; i < Mm*Mm; i += 256){
        double kv = g_Kinv[i], uu = g_uuT[i];
        a1 += kv*(double)g_psi2[i];
        a2 += kv*uu;
        a3 += (double)g_KPK[i]*uu;
        a4 += (double)g_G[i]*uu;
    }
    for (int i = t; i < Mm; i += 256) a5 += log((double)g_L[i*Mm+i]);
    for (int i = t; i < Mm*Dd; i += 256){
        int mm = i/Dd, dd = i%Dd;
        double x = (double)qs[(size_t)mm*Mm*Dd + (size_t)mm*Dd + dd];
        a6 += log(x*x);
    }
    double sums[6] = {a1,a2,a3,a4,a5,a6};
    double res[6];
    for (int s = 0; s < 6; s++){
        red[t] = sums[s];
        __syncthreads();
        for (int w = 128; w > 0; w >>= 1){
            if (t < w) red[t] += red[t+w];
            __syncthreads();
        }
        res[s] = red[0];
        __syncthreads();
    }
    if (t == 0){
        double variance = var_p[0], beta = beta_p[0];
        double psi0 = (double)Nn*variance;
        double lml = -0.5*beta*(double)Dd*(psi0 - res[0]);
        double logdetK = 2.0*res[4];
        double kl = 0.5*(res[1] - (double)(Mm*Dd) + (double)Dd*logdetK - res[5]);
        lml -= kl;
        lml -= 0.5*beta*(res[2] - res[3]);
        out_lml[0] = (float)lml;
    }
}

// ---------------- host launcher ----------------
extern "C" void kernel_launch(void* const* d_in, const int* in_sizes, int n_in,
                              void* d_out, int out_size)
{
    const float* Xmean = (const float*)d_in[0];
    const float* Xvar  = (const float*)d_in[1];
    const float* Z     = (const float*)d_in[2];
    const float* qmu   = (const float*)d_in[3];
    const float* qs    = (const float*)d_in[4];
    const float* ls    = (const float*)d_in[5];
    const float* var_p = (const float*)d_in[6];
    const float* beta_p= (const float*)d_in[7];

    float* out      = (float*)d_out;
    float* out_mean = out;                       // N*D
    float* out_var  = out + Nn*Dd;               // N*D*D
    float* out_lml  = out + Nn*Dd + (size_t)Nn*Dd*Dd; // 1

    float *pPsi1, *pKinv, *pA1, *pR, *puuT, *pP2, *pKPK, *pG, *pTmpF, *pPsi2, *pLinv;
    cudaGetSymbolAddress((void**)&pPsi1, g_psi1);
    cudaGetSymbolAddress((void**)&pKinv, g_Kinv);
    cudaGetSymbolAddress((void**)&pA1,   g_A1);
    cudaGetSymbolAddress((void**)&pR,    g_R);
    cudaGetSymbolAddress((void**)&puuT,  g_uuT);
    cudaGetSymbolAddress((void**)&pP2,   g_P2);
    cudaGetSymbolAddress((void**)&pKPK,  g_KPK);
    cudaGetSymbolAddress((void**)&pG,    g_G);
    cudaGetSymbolAddress((void**)&pTmpF, g_tmpF);
    cudaGetSymbolAddress((void**)&pPsi2, g_psi2);
    cudaGetSymbolAddress((void**)&pLinv, g_Linv);

    // 1. per-n prep
    prep_n_kernel<<<(Nn+255)/256, 256>>>(Xvar, ls);
    // 2. qmk + Kmm
    prep_kmm_kernel<<<(Mm*Mm+255)/256, 256>>>(Z, ls, var_p);
    // 3. psi1
    {
        dim3 b(32,8), g(Mm/32, Nn/8);
        psi1_kernel<<<g, b>>>(Z, Xmean, var_p);
    }
    // 4. psi2 (upper tile-triangle) + mirror
    {
        dim3 b(16,16);
        psi2_kernel2<<<136, b>>>(Z, Xmean, var_p);
        psi2_mirror_kernel<<<(Mm*Mm+255)/256, 256>>>();
    }
    // 5. Cholesky
    cholesky_kernel<<<1, 256>>>();
    // 6. Linv
    trisolve_kernel<<<Mm/32, 256>>>();
    // 7. Kinv = Linv^T Linv
    {
        dim3 g((Mm+63)/64, (Mm+63)/64);
        sgemm<1,0><<<g, 256>>>(Mm, Mm, Mm, pLinv, Mm, pLinv, Mm, pKinv, Mm, 1.f, 0.f);
    }
    // 8. masked R
    maskR_kernel<<<(Mm*Mm*Dd+255)/256, 256>>>(qs);
    // 9. uuT = R R^T + qmu qmu^T
    {
        dim3 g((Mm+63)/64, (Mm+63)/64);
        sgemm<0,1><<<g, 256>>>(Mm, Mm, Mm*Dd, pR, Mm*Dd, pR, Mm*Dd, puuT, Mm, 1.f, 0.f);
        sgemm<0,1><<<g, 256>>>(Mm, Mm, Dd, qmu, Dd, qmu, Dd, puuT, Mm, 1.f, 1.f);
    }
    // 10. A1 = psi1 @ Kinv
    {
        dim3 g((Mm+63)/64, (Nn+63)/64);
        sgemm<0,0><<<g, 256>>>(Nn, Mm, Mm, pPsi1, Mm, pKinv, Mm, pA1, Mm, 1.f, 0.f);
    }
    // 11. forward_mean = A1 @ qmu
    {
        dim3 g((Dd+63)/64, (Nn+63)/64);
        sgemm<0,0><<<g, 256>>>(Nn, Dd, Mm, pA1, Mm, qmu, Dd, out_mean, Dd, 1.f, 0.f);
    }
    // 12. P2 = Kinv @ psi2 ; KPK = P2 @ Kinv
    {
        dim3 g((Mm+63)/64, (Mm+63)/64);
        sgemm<0,0><<<g, 256>>>(Mm, Mm, Mm, pKinv, Mm, pPsi2, Mm, pP2, Mm, 1.f, 0.f);
        sgemm<0,0><<<g, 256>>>(Mm, Mm, Mm, pP2, Mm, pKinv, Mm, pKPK, Mm, 1.f, 0.f);
    }
    // 13. G = A1^T A1
    {
        dim3 g((Mm+63)/64, (Mm+63)/64);
        sgemm<1,0><<<g, 256>>>(Mm, Mm, Nn, pA1, Mm, pA1, Mm, pG, Mm, 1.f, 0.f);
    }
    // 14. tmpF = A1 @ R   (1024 x 8192, K=256)
    {
        dim3 g((Mm*Dd+63)/64, (Nn+63)/64);
        sgemm<0,0><<<g, 256>>>(Nn, Mm*Dd, Mm, pA1, Mm, pR, Mm*Dd, pTmpF, Mm*Dd, 1.f, 0.f);
    }
    // 15. forward_var = batched T^T T + I/beta
    var_kernel<<<Nn, 256>>>(out_var, beta_p);
    // 16. lml
    reduce_lml_kernel<<<1, 256>>>(out_lml, var_p, beta_p, qs);
}

// round 2
// speedup vs baseline: 1.1564x; 1.1564x over previous
#include <cuda_runtime.h>
#include <cuda_bf16.h>
#include <math.h>

#define Nn 1024
#define Qq 32
#define Mm 256
#define Dd 32
#define JITTER 1e-6f
#define TRI (Mm*(Mm+1)/2)   // 32896 packed lower-tri elems

__device__ __forceinline__ int off(int i){ return (i*(i+1))>>1; }

// ---------------- scratch (device globals; no allocation) ----------------
__device__ float g_w1[Nn*Qq];
__device__ float g_w2[Nn*Qq];
__device__ float g_e1[Nn];
__device__ float g_e2[Nn];
__device__ float g_qmk[Mm*Mm];
__device__ float g_Kmm[Mm*Mm];
__device__ float g_Lp[TRI];          // packed lower-tri Cholesky factor
__device__ float g_Linv[Mm*Mm];
__device__ float g_Kinv[Mm*Mm];
__device__ float g_psi1[Nn*Mm];
__device__ float g_psi2[Mm*Mm];
__device__ float g_psi2p[4*Mm*Mm];   // 4 N-chunk partials
__device__ float g_A1[Nn*Mm];
__device__ float g_R[Mm*Mm*Dd];      // 8 MB masked q_sqrt
__device__ float g_uuT[Mm*Mm];
__device__ float g_P2[Mm*Mm];
__device__ float g_KPK[Mm*Mm];
__device__ float g_G[Mm*Mm];
__device__ float g_tmpF[(size_t)Nn*Mm*Dd]; // 32 MB

// ---------------- per-n prep: w1,w2,logdet terms ----------------
__global__ void prep_n_kernel(const float* __restrict__ Xvar,
                              const float* __restrict__ ls)
{
    int n = blockIdx.x*blockDim.x + threadIdx.x;
    if (n >= Nn) return;
    float ld1 = 0.f, ld2 = 0.f;
    #pragma unroll
    for (int q = 0; q < Qq; q++){
        float l = ls[q];
        float l2 = l*l;
        float S = Xvar[n*Qq+q];
        float d1 = l2 + S;
        float d2 = l2 + 2.f*S;
        g_w1[n*Qq+q] = 1.f/d1;
        g_w2[n*Qq+q] = 1.f/d2;
        ld1 += logf(d1/l2);
        ld2 += logf(d2/l2);
    }
    g_e1[n] = -0.5f*ld1;
    g_e2[n] = -0.5f*ld2;
}

// ---------------- qmk and Kmm ----------------
__global__ void prep_kmm_kernel(const float* __restrict__ Z,
                                const float* __restrict__ ls,
                                const float* __restrict__ var_p)
{
    int idx = blockIdx.x*blockDim.x + threadIdx.x;
    if (idx >= Mm*Mm) return;
    int m = idx / Mm, k = idx % Mm;
    float s = 0.f;
    #pragma unroll
    for (int q = 0; q < Qq; q++){
        float l = ls[q];
        float d = Z[m*Qq+q] - Z[k*Qq+q];
        s += (d*d)/(l*l);
    }
    g_qmk[idx] = s;
    float v = var_p[0];
    g_Kmm[idx] = v*expf(-0.5f*s) + ((m==k)?JITTER:0.f);
}

// ---------------- psi1 ----------------
__global__ void psi1_kernel(const float* __restrict__ Z,
                            const float* __restrict__ Xmean,
                            const float* __restrict__ var_p)
{
    int tx = threadIdx.x, ty = threadIdx.y;
    int m = blockIdx.x*32 + tx;
    int n0 = blockIdx.y*8;
    int n = n0 + ty;
    __shared__ float Zs[32][33];
    __shared__ float ws[8][32], ms[8][32], es[8];
    int t = ty*32 + tx;
    for (int i = t; i < 32*Qq; i += 256){
        int r = i/Qq, q = i%Qq;
        Zs[r][q] = Z[(blockIdx.x*32+r)*Qq + q];
    }
    for (int i = t; i < 8*Qq; i += 256){
        int r = i/Qq, q = i%Qq;
        ws[r][q] = g_w1[(n0+r)*Qq + q];
        ms[r][q] = Xmean[(n0+r)*Qq + q];
    }
    if (t < 8) es[t] = g_e1[n0+t];
    __syncthreads();
    float s = 0.f;
    #pragma unroll
    for (int q = 0; q < Qq; q++){
        float d = ms[ty][q] - Zs[tx][q];
        s = fmaf(ws[ty][q], d*d, s);
    }
    g_psi1[n*Mm + m] = var_p[0]*expf(es[ty] - 0.5f*s);
}

// ---------------- psi2 (upper tile-triangle, N split in 4 chunks) ----------------
__global__ void psi2_kernel(const float* __restrict__ Z,
                            const float* __restrict__ Xmean)
{
    int rem = blockIdx.x, bi = 0;
    for (bi = 0; bi < 16; bi++){ int len = 16-bi; if (rem < len) break; rem -= len; }
    int bj = bi + rem;
    int chunk = blockIdx.y;
    int tx = threadIdx.x, ty = threadIdx.y;
    int m = bi*16 + ty;
    int k = bj*16 + tx;
    int t = ty*16 + tx;

    __shared__ float Zm[16][33], Zk[16][33];
    for (int i = t; i < 16*Qq; i += 256){
        int r = i/Qq, q = i%Qq;
        Zm[r][q] = Z[(bi*16+r)*Qq + q];
        Zk[r][q] = Z[(bj*16+r)*Qq + q];
    }
    __syncthreads();
    float zbar[Qq];
    #pragma unroll
    for (int q = 0; q < Qq; q++) zbar[q] = 0.5f*(Zm[ty][q] + Zk[tx][q]);
    float base = -0.25f*g_qmk[m*Mm + k];

    __shared__ float wb[16][33], mb[16][33], eb[16];
    float acc = 0.f;
    int nbeg = chunk*(Nn/4), nend = nbeg + Nn/4;
    for (int n0 = nbeg; n0 < nend; n0 += 16){
        __syncthreads();
        for (int i = t; i < 16*Qq; i += 256){
            int r = i/Qq, q = i%Qq;
            wb[r][q] = g_w2[(n0+r)*Qq + q];
            mb[r][q] = Xmean[(n0+r)*Qq + q];
        }
        if (t < 16) eb[t] = g_e2[n0+t];
        __syncthreads();
        #pragma unroll 2
        for (int nn = 0; nn < 16; nn++){
            float r = 0.f;
            #pragma unroll
            for (int q = 0; q < Qq; q++){
                float d = mb[nn][q] - zbar[q];
                r = fmaf(wb[nn][q], d*d, r);
            }
            acc += __expf(base + eb[nn] - r);
        }
    }
    g_psi2p[chunk*(Mm*Mm) + m*Mm + k] = acc;
}

// combine 4 partials, apply var^2, mirror lower tiles
__global__ void psi2_combine_kernel(const float* __restrict__ var_p)
{
    int idx = blockIdx.x*blockDim.x + threadIdx.x;
    if (idx >= Mm*Mm) return;
    int m = idx / Mm, k = idx % Mm;
    int src = ((m>>4) <= (k>>4)) ? (m*Mm + k) : (k*Mm + m);
    float s = g_psi2p[src] + g_psi2p[Mm*Mm + src]
            + g_psi2p[2*Mm*Mm + src] + g_psi2p[3*Mm*Mm + src];
    float v = var_p[0];
    g_psi2[idx] = v*v*s;
}

// ---------------- Cholesky of Kmm (single block, packed triangle in smem) ----------------
__global__ void cholesky_kernel()
{
    extern __shared__ float sL[];      // TRI floats = 131584 B
    __shared__ float colk[Mm];
    int t = threadIdx.x;
    // load packed lower triangle
    for (int i = 0; i < Mm; i++)
        for (int j = t; j <= i; j += 256)
            sL[off(i)+j] = g_Kmm[i*Mm+j];
    __syncthreads();
    int rl = t>>3, cl = t&7;
    for (int k = 0; k < Mm; k++){
        if (t == 0) sL[off(k)+k] = sqrtf(sL[off(k)+k]);
        __syncthreads();
        float inv = 1.f/sL[off(k)+k];
        float v = 0.f;
        if (t > k){ v = sL[off(t)+k]*inv; sL[off(t)+k] = v; }
        colk[t] = v;
        __syncthreads();
        for (int i = k+1+rl; i < Mm; i += 32){
            float ci = colk[i];
            int b = off(i);
            for (int j = k+1+cl; j <= i; j += 8)
                sL[b+j] -= ci*colk[j];
        }
        __syncthreads();
    }
    for (int i = 0; i < Mm; i++)
        for (int j = t; j <= i; j += 256)
            g_Lp[off(i)+j] = sL[off(i)+j];
}

// ---------------- Linv = L^{-1}: forward substitution, L + X both in smem ----------------
__global__ void trisolve_kernel()
{
    extern __shared__ float sm[];      // sLp[TRI] + Xs[256*33]
    float* sLp = sm;
    float* Xs  = sm + TRI;
    int c0 = blockIdx.x*32;
    int t = threadIdx.x;
    for (int i = t; i < TRI; i += 256) sLp[i] = g_Lp[i];
    for (int i = t; i < Mm*33; i += 256) Xs[i] = 0.f;
    __syncthreads();
    if (t < 32) Xs[(c0+t)*33 + t] = 1.f;
    __syncthreads();
    int c = t&31, ro = t>>5;
    for (int j = c0; j < Mm; j++){
        if (t < 32) Xs[j*33+t] *= (1.f/sLp[off(j)+j]);
        __syncthreads();
        float xjc = Xs[j*33+c];
        for (int i = j+1+ro; i < Mm; i += 8)
            Xs[i*33+c] -= sLp[off(i)+j]*xjc;
        __syncthreads();
    }
    for (int i = t; i < Mm*32; i += 256){
        int r = i>>5, cc = i&31;
        g_Linv[r*Mm + c0 + cc] = Xs[r*33+cc];
    }
}

// ---------------- masked R from q_sqrt ----------------
__global__ void maskR_kernel(const float* __restrict__ qs)
{
    int idx = blockIdx.x*blockDim.x + threadIdx.x;
    if (idx >= Mm*Mm*Dd) return;
    int a = idx / (Mm*Dd);
    int b = (idx / Dd) % Mm;
    g_R[idx] = (b <= a) ? qs[idx] : 0.f;
}

// ---------------- generic SGEMM: C = alpha*op(A)op(B) + beta*C ----------------
template<int TA, int TB>
__global__ void sgemm(int M_, int N_, int K_,
                      const float* __restrict__ A, int lda,
                      const float* __restrict__ B, int ldb,
                      float* __restrict__ C, int ldc,
                      float alpha, float beta)
{
    const int BM = 64, BN = 64, BK = 16;
    __shared__ float As[BK][BM+1];
    __shared__ float Bs[BK][BN+1];
    int bm = blockIdx.y*BM, bn = blockIdx.x*BN;
    int tid = threadIdx.x;
    int tm = (tid/16)*4, tn = (tid%16)*4;
    float acc[4][4] = {};
    for (int k0 = 0; k0 < K_; k0 += BK){
        if (!TA){
            for (int i = tid; i < BM*BK; i += 256){
                int kk = i%BK, mm = i/BK;
                int gm = bm+mm, gk = k0+kk;
                As[kk][mm] = (gm < M_ && gk < K_) ? A[(size_t)gm*lda + gk] : 0.f;
            }
        } else {
            for (int i = tid; i < BM*BK; i += 256){
                int mm = i%BM, kk = i/BM;
                int gm = bm+mm, gk = k0+kk;
                As[kk][mm] = (gm < M_ && gk < K_) ? A[(size_t)gk*lda + gm] : 0.f;
            }
        }
        if (!TB){
            for (int i = tid; i < BN*BK; i += 256){
                int nn = i%BN, kk = i/BN;
                int gn = bn+nn, gk = k0+kk;
                Bs[kk][nn] = (gn < N_ && gk < K_) ? B[(size_t)gk*ldb + gn] : 0.f;
            }
        } else {
            for (int i = tid; i < BN*BK; i += 256){
                int kk = i%BK, nn = i/BK;
                int gn = bn+nn, gk = k0+kk;
                Bs[kk][nn] = (gn < N_ && gk < K_) ? B[(size_t)gn*ldb + gk] : 0.f;
            }
        }
        __syncthreads();
        #pragma unroll
        for (int kk = 0; kk < BK; kk++){
            float ra[4], rb[4];
            #pragma unroll
            for (int i = 0; i < 4; i++){ ra[i] = As[kk][tm+i]; rb[i] = Bs[kk][tn+i]; }
            #pragma unroll
            for (int i = 0; i < 4; i++)
                #pragma unroll
                for (int j = 0; j < 4; j++)
                    acc[i][j] = fmaf(ra[i], rb[j], acc[i][j]);
        }
        __syncthreads();
    }
    #pragma unroll
    for (int i = 0; i < 4; i++){
        int gm = bm + tm + i;
        if (gm >= M_) continue;
        #pragma unroll
        for (int j = 0; j < 4; j++){
            int gn = bn + tn + j;
            if (gn >= N_) continue;
            float prev = (beta != 0.f) ? C[(size_t)gm*ldc + gn] : 0.f;
            C[(size_t)gm*ldc + gn] = alpha*acc[i][j] + beta*prev;
        }
    }
}

// ---------------- batched SYRK for forward_var ----------------
__global__ void var_kernel(float* __restrict__ out_var, const float* __restrict__ beta_p)
{
    __shared__ float T[Mm*Dd]; // 32 KB
    int n = blockIdx.x;
    int t = threadIdx.x;
    for (int i = t; i < Mm*Dd; i += 256) T[i] = g_tmpF[(size_t)n*(Mm*Dd) + i];
    __syncthreads();
    float invb = 1.f/beta_p[0];
    int e = t & 31, d0 = (t >> 5)*4;
    float a0=0.f, a1=0.f, a2=0.f, a3=0.f;
    for (int m = 0; m < Mm; m++){
        float te = T[m*32 + e];
        a0 = fmaf(T[m*32 + d0+0], te, a0);
        a1 = fmaf(T[m*32 + d0+1], te, a1);
        a2 = fmaf(T[m*32 + d0+2], te, a2);
        a3 = fmaf(T[m*32 + d0+3], te, a3);
    }
    float* vp = out_var + (size_t)n*Dd*Dd;
    vp[(d0+0)*32 + e] = a0 + ((d0+0)==e ? invb : 0.f);
    vp[(d0+1)*32 + e] = a1 + ((d0+1)==e ? invb : 0.f);
    vp[(d0+2)*32 + e] = a2 + ((d0+2)==e ? invb : 0.f);
    vp[(d0+3)*32 + e] = a3 + ((d0+3)==e ? invb : 0.f);
}

// ---------------- final scalar reduction -> lml ----------------
__global__ void reduce_lml_kernel(float* __restrict__ out_lml,
                                  const float* __restrict__ var_p,
                                  const float* __restrict__ beta_p,
                                  const float* __restrict__ qs)
{
    __shared__ double red[256];
    int t = threadIdx.x;
    double a1=0, a2=0, a3=0, a4=0, a5=0, a6=0;
    for (int i = t; i < Mm*Mm; i += 256){
        double kv = g_Kinv[i], uu = g_uuT[i];
        a1 += kv*(double)g_psi2[i];
        a2 += kv*uu;
        a3 += (double)g_KPK[i]*uu;
        a4 += (double)g_G[i]*uu;
    }
    for (int i = t; i < Mm; i += 256) a5 += log((double)g_Lp[off(i)+i]);
    for (int i = t; i < Mm*Dd; i += 256){
        int mm = i/Dd, dd = i%Dd;
        double x = (double)qs[(size_t)mm*Mm*Dd + (size_t)mm*Dd + dd];
        a6 += log(x*x);
    }
    double sums[6] = {a1,a2,a3,a4,a5,a6};
    double res[6];
    for (int s = 0; s < 6; s++){
        red[t] = sums[s];
        __syncthreads();
        for (int w = 128; w > 0; w >>= 1){
            if (t < w) red[t] += red[t+w];
            __syncthreads();
        }
        res[s] = red[0];
        __syncthreads();
    }
    if (t == 0){
        double variance = var_p[0], beta = beta_p[0];
        double psi0 = (double)Nn*variance;
        double lml = -0.5*beta*(double)Dd*(psi0 - res[0]);
        double logdetK = 2.0*res[4];
        double kl = 0.5*(res[1] - (double)(Mm*Dd) + (double)Dd*logdetK - res[5]);
        lml -= kl;
        lml -= 0.5*beta*(res[2] - res[3]);
        out_lml[0] = (float)lml;
    }
}

// ---------------- host launcher ----------------
extern "C" void kernel_launch(void* const* d_in, const int* in_sizes, int n_in,
                              void* d_out, int out_size)
{
    const float* Xmean = (const float*)d_in[0];
    const float* Xvar  = (const float*)d_in[1];
    const float* Z     = (const float*)d_in[2];
    const float* qmu   = (const float*)d_in[3];
    const float* qs    = (const float*)d_in[4];
    const float* ls    = (const float*)d_in[5];
    const float* var_p = (const float*)d_in[6];
    const float* beta_p= (const float*)d_in[7];

    float* out      = (float*)d_out;
    float* out_mean = out;                       // N*D
    float* out_var  = out + Nn*Dd;               // N*D*D
    float* out_lml  = out + Nn*Dd + (size_t)Nn*Dd*Dd; // 1

    float *pPsi1, *pKinv, *pA1, *pR, *puuT, *pP2, *pKPK, *pG, *pTmpF, *pPsi2, *pLinv;
    cudaGetSymbolAddress((void**)&pPsi1, g_psi1);
    cudaGetSymbolAddress((void**)&pKinv, g_Kinv);
    cudaGetSymbolAddress((void**)&pA1,   g_A1);
    cudaGetSymbolAddress((void**)&pR,    g_R);
    cudaGetSymbolAddress((void**)&puuT,  g_uuT);
    cudaGetSymbolAddress((void**)&pP2,   g_P2);
    cudaGetSymbolAddress((void**)&pKPK,  g_KPK);
    cudaGetSymbolAddress((void**)&pG,    g_G);
    cudaGetSymbolAddress((void**)&pTmpF, g_tmpF);
    cudaGetSymbolAddress((void**)&pPsi2, g_psi2);
    cudaGetSymbolAddress((void**)&pLinv, g_Linv);

    // opt-in large dynamic smem (idempotent)
    const int CHOL_SMEM = TRI*4;                 // 131584
    const int TRIS_SMEM = TRI*4 + Mm*33*4;       // 165376
    cudaFuncSetAttribute(cholesky_kernel, cudaFuncAttributeMaxDynamicSharedMemorySize, CHOL_SMEM);
    cudaFuncSetAttribute(trisolve_kernel, cudaFuncAttributeMaxDynamicSharedMemorySize, TRIS_SMEM);

    // 1. per-n prep
    prep_n_kernel<<<(Nn+255)/256, 256>>>(Xvar, ls);
    // 2. qmk + Kmm
    prep_kmm_kernel<<<(Mm*Mm+255)/256, 256>>>(Z, ls, var_p);
    // 3. psi1
    {
        dim3 b(32,8), g(Mm/32, Nn/8);
        psi1_kernel<<<g, b>>>(Z, Xmean, var_p);
    }
    // 4. psi2 (upper tile-triangle, 4 N-chunks) + combine/mirror
    {
        dim3 b(16,16), g(136, 4);
        psi2_kernel<<<g, b>>>(Z, Xmean);
        psi2_combine_kernel<<<(Mm*Mm+255)/256, 256>>>(var_p);
    }
    // 5. Cholesky (smem-resident)
    cholesky_kernel<<<1, 256, CHOL_SMEM>>>();
    // 6. Linv (smem-resident)
    trisolve_kernel<<<Mm/32, 256, TRIS_SMEM>>>();
    // 7. Kinv = Linv^T Linv
    {
        dim3 g((Mm+63)/64, (Mm+63)/64);
        sgemm<1,0><<<g, 256>>>(Mm, Mm, Mm, pLinv, Mm, pLinv, Mm, pKinv, Mm, 1.f, 0.f);
    }
    // 8. masked R
    maskR_kernel<<<(Mm*Mm*Dd+255)/256, 256>>>(qs);
    // 9. uuT = R R^T + qmu qmu^T
    {
        dim3 g((Mm+63)/64, (Mm+63)/64);
        sgemm<0,1><<<g, 256>>>(Mm, Mm, Mm*Dd, pR, Mm*Dd, pR, Mm*Dd, puuT, Mm, 1.f, 0.f);
        sgemm<0,1><<<g, 256>>>(Mm, Mm, Dd, qmu, Dd, qmu, Dd, puuT, Mm, 1.f, 1.f);
    }
    // 10. A1 = psi1 @ Kinv
    {
        dim3 g((Mm+63)/64, (Nn+63)/64);
        sgemm<0,0><<<g, 256>>>(Nn, Mm, Mm, pPsi1, Mm, pKinv, Mm, pA1, Mm, 1.f, 0.f);
    }
    // 11. forward_mean = A1 @ qmu
    {
        dim3 g((Dd+63)/64, (Nn+63)/64);
        sgemm<0,0><<<g, 256>>>(Nn, Dd, Mm, pA1, Mm, qmu, Dd, out_mean, Dd, 1.f, 0.f);
    }
    // 12. P2 = Kinv @ psi2 ; KPK = P2 @ Kinv
    {
        dim3 g((Mm+63)/64, (Mm+63)/64);
        sgemm<0,0><<<g, 256>>>(Mm, Mm, Mm, pKinv, Mm, pPsi2, Mm, pP2, Mm, 1.f, 0.f);
        sgemm<0,0><<<g, 256>>>(Mm, Mm, Mm, pP2, Mm, pKinv, Mm, pKPK, Mm, 1.f, 0.f);
    }
    // 13. G = A1^T A1
    {
        dim3 g((Mm+63)/64, (Mm+63)/64);
        sgemm<1,0><<<g, 256>>>(Mm, Mm, Nn, pA1, Mm, pA1, Mm, pG, Mm, 1.f, 0.f);
    }
    // 14. tmpF = A1 @ R   (1024 x 8192, K=256)
    {
        dim3 g((Mm*Dd+63)/64, (Nn+63)/64);
        sgemm<0,0><<<g, 256>>>(Nn, Mm*Dd, Mm, pA1, Mm, pR, Mm*Dd, pTmpF, Mm*Dd, 1.f, 0.f);
    }
    // 15. forward_var = batched T^T T + I/beta
    var_kernel<<<Nn, 256>>>(out_var, beta_p);
    // 16. lml
    reduce_lml_kernel<<<1, 256>>>(out_lml, var_p, beta_p, qs);
}

// round 3
// speedup vs baseline: 2.0711x; 1.7911x over previous
#include <cuda_runtime.h>
#include <cuda_bf16.h>
#include <math.h>

#define Nn 1024
#define Qq 32
#define Mm 256
#define Dd 32
#define JITTER 1e-6f
#define TRI (Mm*(Mm+1)/2)   // 32896 packed lower-tri elems

__device__ __forceinline__ int off(int i){ return (i*(i+1))>>1; }

// ---------------- scratch (device globals; no allocation) ----------------
__device__ float g_hw1[Nn*Qq];       // 0.5*w1
__device__ float g_wm1[Nn*Qq];       // w1*mu
__device__ float g_hw2[Nn*Qq];       // 0.5*w2
__device__ float g_w2[Nn*Qq];
__device__ float g_wm2[Nn*Qq];       // w2*mu
__device__ float g_G1[Nn];           // e1 - 0.5*A1sum
__device__ float g_F2[Nn];           // e2 - A2sum
__device__ float g_E2[Nn*Mm];        // B2 - 0.25*C2
__device__ float g_qmk[Mm*Mm];
__device__ float g_Kmm[Mm*Mm];
__device__ float g_Lp[TRI];          // packed lower-tri Cholesky factor
__device__ float g_Linv[Mm*Mm];
__device__ float g_Kinv[Mm*Mm];
__device__ float g_psi1[Nn*Mm];
__device__ float g_psi2[Mm*Mm];
__device__ float g_psi2p[4*Mm*Mm];   // 4 N-chunk partials
__device__ float g_A1[Nn*Mm];
__device__ float g_R[Mm*Mm*Dd];      // 8 MB masked q_sqrt
__device__ float g_uuT[Mm*Mm];
__device__ float g_uuTp[16*Mm*Mm];   // 4 MB split-K partials
__device__ float g_Gp[8*Mm*Mm];      // 2 MB split-K partials
__device__ float g_P2[Mm*Mm];
__device__ float g_KPK[Mm*Mm];
__device__ float g_G[Mm*Mm];
__device__ float g_tmpF[(size_t)Nn*Mm*Dd]; // 32 MB

// ---------------- per-n prep ----------------
__global__ void prep_n_kernel(const float* __restrict__ Xmean,
                              const float* __restrict__ Xvar,
                              const float* __restrict__ ls)
{
    int n = blockIdx.x*blockDim.x + threadIdx.x;
    if (n >= Nn) return;
    float ld1 = 0.f, ld2 = 0.f, a1 = 0.f, a2 = 0.f;
    #pragma unroll
    for (int q = 0; q < Qq; q++){
        float l = ls[q];
        float l2 = l*l;
        float S = Xvar[n*Qq+q];
        float mu = Xmean[n*Qq+q];
        float d1 = l2 + S;
        float d2 = l2 + 2.f*S;
        float w1 = 1.f/d1;
        float w2 = 1.f/d2;
        g_hw1[n*Qq+q] = 0.5f*w1;
        g_hw2[n*Qq+q] = 0.5f*w2;
        g_w2[n*Qq+q]  = w2;
        g_wm1[n*Qq+q] = w1*mu;
        g_wm2[n*Qq+q] = w2*mu;
        ld1 += logf(d1/l2);
        ld2 += logf(d2/l2);
        a1 = fmaf(w1*mu, mu, a1);
        a2 = fmaf(w2*mu, mu, a2);
    }
    g_G1[n] = -0.5f*ld1 - 0.5f*a1;
    g_F2[n] = -0.5f*ld2 - a2;
}

// ---------------- qmk and Kmm ----------------
__global__ void prep_kmm_kernel(const float* __restrict__ Z,
                                const float* __restrict__ ls,
                                const float* __restrict__ var_p)
{
    int idx = blockIdx.x*blockDim.x + threadIdx.x;
    if (idx >= Mm*Mm) return;
    int m = idx / Mm, k = idx % Mm;
    float s = 0.f;
    #pragma unroll
    for (int q = 0; q < Qq; q++){
        float l = ls[q];
        float d = Z[m*Qq+q] - Z[k*Qq+q];
        s += (d*d)/(l*l);
    }
    g_qmk[idx] = s;
    float v = var_p[0];
    g_Kmm[idx] = v*expf(-0.5f*s) + ((m==k)?JITTER:0.f);
}

// ---------------- E2[n,m] = sum_q Z*(wm2 - 0.25*w2*Z) ----------------
__global__ void e2_kernel(const float* __restrict__ Z)
{
    int tx = threadIdx.x, ty = threadIdx.y;
    int m = blockIdx.x*32 + tx;
    int n0 = blockIdx.y*8;
    int n = n0 + ty;
    __shared__ float Zs[32][33];
    __shared__ float wb[8][32], wmb[8][32];
    int t = ty*32 + tx;
    for (int i = t; i < 32*Qq; i += 256){
        int r = i/Qq, q = i%Qq;
        Zs[r][q] = Z[(blockIdx.x*32+r)*Qq + q];
    }
    for (int i = t; i < 8*Qq; i += 256){
        int r = i/Qq, q = i%Qq;
        wb[r][q]  = g_w2[(n0+r)*Qq + q];
        wmb[r][q] = g_wm2[(n0+r)*Qq + q];
    }
    __syncthreads();
    float s = 0.f;
    #pragma unroll
    for (int q = 0; q < Qq; q++){
        float z = Zs[tx][q];
        float tmp = fmaf(-0.25f*wb[ty][q], z, wmb[ty][q]);
        s = fmaf(tmp, z, s);
    }
    g_E2[n*Mm + m] = s;
}

// ---------------- psi1 = var*exp(G1[n] + sum_q Z*(wm1 - hw1*Z)) ----------------
__global__ void psi1_kernel(const float* __restrict__ Z,
                            const float* __restrict__ var_p)
{
    int tx = threadIdx.x, ty = threadIdx.y;
    int m = blockIdx.x*32 + tx;
    int n0 = blockIdx.y*8;
    int n = n0 + ty;
    __shared__ float Zs[32][33];
    __shared__ float wb[8][32], wmb[8][32], gs[8];
    int t = ty*32 + tx;
    for (int i = t; i < 32*Qq; i += 256){
        int r = i/Qq, q = i%Qq;
        Zs[r][q] = Z[(blockIdx.x*32+r)*Qq + q];
    }
    for (int i = t; i < 8*Qq; i += 256){
        int r = i/Qq, q = i%Qq;
        wb[r][q]  = g_hw1[(n0+r)*Qq + q];
        wmb[r][q] = g_wm1[(n0+r)*Qq + q];
    }
    if (t < 8) gs[t] = g_G1[n0+t];
    __syncthreads();
    float s = 0.f;
    #pragma unroll
    for (int q = 0; q < Qq; q++){
        float z = Zs[tx][q];
        float tmp = fmaf(-wb[ty][q], z, wmb[ty][q]);
        s = fmaf(tmp, z, s);
    }
    g_psi1[n*Mm + m] = var_p[0]*__expf(gs[ty] + s);
}

// ---------------- psi2 (upper tile-triangle, N split in 4 chunks) ----------------
__global__ void psi2_kernel(const float* __restrict__ Z)
{
    int rem = blockIdx.x, bi = 0;
    for (bi = 0; bi < 16; bi++){ int len = 16-bi; if (rem < len) break; rem -= len; }
    int bj = bi + rem;
    int chunk = blockIdx.y;
    int tx = threadIdx.x, ty = threadIdx.y;
    int m = bi*16 + ty;
    int k = bj*16 + tx;
    int t = ty*16 + tx;

    __shared__ float Zm[16][33], Zk[16][33];
    for (int i = t; i < 16*Qq; i += 256){
        int r = i/Qq, q = i%Qq;
        Zm[r][q] = Z[(bi*16+r)*Qq + q];
        Zk[r][q] = Z[(bj*16+r)*Qq + q];
    }
    __syncthreads();
    float zp[Qq];
    #pragma unroll
    for (int q = 0; q < Qq; q++) zp[q] = Zm[ty][q]*Zk[tx][q];
    float base = -0.25f*g_qmk[m*Mm + k];

    __shared__ float wb[16][33], F2s[16];
    __shared__ float Em[16][17], Ek[16][17];
    float acc = 0.f;
    int nbeg = chunk*(Nn/4), nend = nbeg + Nn/4;
    for (int n0 = nbeg; n0 < nend; n0 += 16){
        __syncthreads();
        for (int i = t; i < 16*Qq; i += 256){
            int r = i/Qq, q = i%Qq;
            wb[r][q] = g_hw2[(n0+r)*Qq + q];
        }
        // Em[nn][r] = E2[(n0+nn), bi*16+r]; Ek likewise for bj
        {
            int nn = t >> 4, r = t & 15;
            Em[nn][r] = g_E2[(n0+nn)*Mm + bi*16 + r];
            Ek[nn][r] = g_E2[(n0+nn)*Mm + bj*16 + r];
        }
        if (t < 16) F2s[t] = g_F2[n0+t];
        __syncthreads();
        #pragma unroll 2
        for (int nn = 0; nn < 16; nn++){
            float dot = 0.f;
            #pragma unroll
            for (int q = 0; q < Qq; q++)
                dot = fmaf(wb[nn][q], zp[q], dot);
            float e = base + F2s[nn] + Em[nn][ty] + Ek[nn][tx] - dot;
            acc += __expf(e);
        }
    }
    g_psi2p[chunk*(Mm*Mm) + m*Mm + k] = acc;
}

// combine 4 partials, apply var^2, mirror lower tiles
__global__ void psi2_combine_kernel(const float* __restrict__ var_p)
{
    int idx = blockIdx.x*blockDim.x + threadIdx.x;
    if (idx >= Mm*Mm) return;
    int m = idx / Mm, k = idx % Mm;
    int src = ((m>>4) <= (k>>4)) ? (m*Mm + k) : (k*Mm + m);
    float s = g_psi2p[src] + g_psi2p[Mm*Mm + src]
            + g_psi2p[2*Mm*Mm + src] + g_psi2p[3*Mm*Mm + src];
    float v = var_p[0];
    g_psi2[idx] = v*v*s;
}

// ---------------- Cholesky of Kmm (single block, packed triangle in smem) ----------------
__global__ void cholesky_kernel()
{
    extern __shared__ float sL[];      // TRI floats
    __shared__ float colk[Mm];
    int t = threadIdx.x;
    for (int i = 0; i < Mm; i++)
        for (int j = t; j <= i; j += 256)
            sL[off(i)+j] = g_Kmm[i*Mm+j];
    __syncthreads();
    int rl = t>>3, cl = t&7;
    for (int k = 0; k < Mm; k++){
        if (t == 0) sL[off(k)+k] = sqrtf(sL[off(k)+k]);
        __syncthreads();
        float inv = 1.f/sL[off(k)+k];
        float v = 0.f;
        if (t > k){ v = sL[off(t)+k]*inv; sL[off(t)+k] = v; }
        colk[t] = v;
        __syncthreads();
        for (int i = k+1+rl; i < Mm; i += 32){
            float ci = colk[i];
            int b = off(i);
            for (int j = k+1+cl; j <= i; j += 8)
                sL[b+j] -= ci*colk[j];
        }
        __syncthreads();
    }
    for (int i = 0; i < Mm; i++)
        for (int j = t; j <= i; j += 256)
            g_Lp[off(i)+j] = sL[off(i)+j];
}

// ---------------- Linv = L^{-1}: forward substitution, L + X both in smem ----------------
__global__ void trisolve_kernel()
{
    extern __shared__ float sm[];      // sLp[TRI] + Xs[256*33]
    float* sLp = sm;
    float* Xs  = sm + TRI;
    int c0 = blockIdx.x*32;
    int t = threadIdx.x;
    for (int i = t; i < TRI; i += 256) sLp[i] = g_Lp[i];
    for (int i = t; i < Mm*33; i += 256) Xs[i] = 0.f;
    __syncthreads();
    if (t < 32) Xs[(c0+t)*33 + t] = 1.f;
    __syncthreads();
    int c = t&31, ro = t>>5;
    for (int j = c0; j < Mm; j++){
        if (t < 32) Xs[j*33+t] *= (1.f/sLp[off(j)+j]);
        __syncthreads();
        float xjc = Xs[j*33+c];
        for (int i = j+1+ro; i < Mm; i += 8)
            Xs[i*33+c] -= sLp[off(i)+j]*xjc;
        __syncthreads();
    }
    for (int i = t; i < Mm*32; i += 256){
        int r = i>>5, cc = i&31;
        g_Linv[r*Mm + c0 + cc] = Xs[r*33+cc];
    }
}

// ---------------- masked R from q_sqrt ----------------
__global__ void maskR_kernel(const float* __restrict__ qs)
{
    int idx = blockIdx.x*blockDim.x + threadIdx.x;
    if (idx >= Mm*Mm*Dd) return;
    int a = idx / (Mm*Dd);
    int b = (idx / Dd) % Mm;
    g_R[idx] = (b <= a) ? qs[idx] : 0.f;
}

// ---------------- 64x64 SGEMM (small matrices) ----------------
template<int TA, int TB>
__global__ void sgemm(int M_, int N_, int K_,
                      const float* __restrict__ A, int lda,
                      const float* __restrict__ B, int ldb,
                      float* __restrict__ C, int ldc,
                      float alpha, float beta)
{
    const int BM = 64, BN = 64, BK = 16;
    __shared__ float As[BK][BM+1];
    __shared__ float Bs[BK][BN+1];
    int bm = blockIdx.y*BM, bn = blockIdx.x*BN;
    int tid = threadIdx.x;
    int tm = (tid/16)*4, tn = (tid%16)*4;
    float acc[4][4] = {};
    for (int k0 = 0; k0 < K_; k0 += BK){
        if (!TA){
            for (int i = tid; i < BM*BK; i += 256){
                int kk = i%BK, mm = i/BK;
                int gm = bm+mm, gk = k0+kk;
                As[kk][mm] = (gm < M_ && gk < K_) ? A[(size_t)gm*lda + gk] : 0.f;
            }
        } else {
            for (int i = tid; i < BM*BK; i += 256){
                int mm = i%BM, kk = i/BM;
                int gm = bm+mm, gk = k0+kk;
                As[kk][mm] = (gm < M_ && gk < K_) ? A[(size_t)gk*lda + gm] : 0.f;
            }
        }
        if (!TB){
            for (int i = tid; i < BN*BK; i += 256){
                int nn = i%BN, kk = i/BN;
                int gn = bn+nn, gk = k0+kk;
                Bs[kk][nn] = (gn < N_ && gk < K_) ? B[(size_t)gk*ldb + gn] : 0.f;
            }
        } else {
            for (int i = tid; i < BN*BK; i += 256){
                int kk = i%BK, nn = i/BK;
                int gn = bn+nn, gk = k0+kk;
                Bs[kk][nn] = (gn < N_ && gk < K_) ? B[(size_t)gn*ldb + gk] : 0.f;
            }
        }
        __syncthreads();
        #pragma unroll
        for (int kk = 0; kk < BK; kk++){
            float ra[4], rb[4];
            #pragma unroll
            for (int i = 0; i < 4; i++){ ra[i] = As[kk][tm+i]; rb[i] = Bs[kk][tn+i]; }
            #pragma unroll
            for (int i = 0; i < 4; i++)
                #pragma unroll
                for (int j = 0; j < 4; j++)
                    acc[i][j] = fmaf(ra[i], rb[j], acc[i][j]);
        }
        __syncthreads();
    }
    #pragma unroll
    for (int i = 0; i < 4; i++){
        int gm = bm + tm + i;
        if (gm >= M_) continue;
        #pragma unroll
        for (int j = 0; j < 4; j++){
            int gn = bn + tn + j;
            if (gn >= N_) continue;
            float prev = (beta != 0.f) ? C[(size_t)gm*ldc + gn] : 0.f;
            C[(size_t)gm*ldc + gn] = alpha*acc[i][j] + beta*prev;
        }
    }
}

// ---------------- 128x128 SGEMM, 8x8/thread, optional split-K via blockIdx.z ----------------
// Requires M_%128==0, N_%128==0, Kchunk%16==0. Writes C + z*partStride.
template<int TA, int TB>
__global__ void sgemm128(int M_, int N_, int K_, int Kchunk,
                         const float* __restrict__ A, int lda,
                         const float* __restrict__ B, int ldb,
                         float* __restrict__ C, int ldc, size_t partStride)
{
    const int BM = 128, BN = 128, BK = 16;
    __shared__ float As[BK][BM+4];
    __shared__ float Bs[BK][BN+4];
    int bm = blockIdx.y*BM, bn = blockIdx.x*BN;
    int kbeg = blockIdx.z*Kchunk;
    int kend = kbeg + Kchunk; if (kend > K_) kend = K_;
    float* Cb = C + (size_t)blockIdx.z*partStride;
    int tid = threadIdx.x;
    int tm = (tid/16)*8, tn = (tid%16)*8;
    float acc[8][8] = {};
    for (int k0 = kbeg; k0 < kend; k0 += BK){
        if (!TA){
            #pragma unroll
            for (int i = tid; i < BM*BK; i += 256){
                int kk = i%BK, mm = i/BK;
                As[kk][mm] = A[(size_t)(bm+mm)*lda + (k0+kk)];
            }
        } else {
            #pragma unroll
            for (int i = tid; i < BM*BK; i += 256){
                int mm = i%BM, kk = i/BM;
                As[kk][mm] = A[(size_t)(k0+kk)*lda + (bm+mm)];
            }
        }
        if (!TB){
            #pragma unroll
            for (int i = tid; i < BN*BK; i += 256){
                int nn = i%BN, kk = i/BN;
                Bs[kk][nn] = B[(size_t)(k0+kk)*ldb + (bn+nn)];
            }
        } else {
            #pragma unroll
            for (int i = tid; i < BN*BK; i += 256){
                int kk = i%BK, nn = i/BK;
                Bs[kk][nn] = B[(size_t)(bn+nn)*ldb + (k0+kk)];
            }
        }
        __syncthreads();
        #pragma unroll
        for (int kk = 0; kk < BK; kk++){
            float ra[8], rb[8];
            *(float4*)&ra[0] = *(const float4*)&As[kk][tm];
            *(float4*)&ra[4] = *(const float4*)&As[kk][tm+4];
            *(float4*)&rb[0] = *(const float4*)&Bs[kk][tn];
            *(float4*)&rb[4] = *(const float4*)&Bs[kk][tn+4];
            #pragma unroll
            for (int i = 0; i < 8; i++)
                #pragma unroll
                for (int j = 0; j < 8; j++)
                    acc[i][j] = fmaf(ra[i], rb[j], acc[i][j]);
        }
        __syncthreads();
    }
    #pragma unroll
    for (int i = 0; i < 8; i++){
        float* cp = Cb + (size_t)(bm+tm+i)*ldc + bn + tn;
        *(float4*)cp       = *(float4*)&acc[i][0];
        *(float4*)(cp + 4) = *(float4*)&acc[i][4];
    }
}

// ---------------- sum split-K partials into out ----------------
__global__ void reduce_parts_kernel(float* __restrict__ out,
                                    const float* __restrict__ parts,
                                    int S, int MN, int addBase)
{
    int idx = blockIdx.x*blockDim.x + threadIdx.x;
    if (idx >= MN) return;
    float s = addBase ? out[idx] : 0.f;
    for (int i = 0; i < S; i++) s += parts[(size_t)i*MN + idx];
    out[idx] = s;
}

// ---------------- batched SYRK for forward_var ----------------
__global__ void var_kernel(float* __restrict__ out_var, const float* __restrict__ beta_p)
{
    __shared__ float T[Mm*Dd]; // 32 KB
    int n = blockIdx.x;
    int t = threadIdx.x;
    for (int i = t; i < Mm*Dd; i += 256) T[i] = g_tmpF[(size_t)n*(Mm*Dd) + i];
    __syncthreads();
    float invb = 1.f/beta_p[0];
    int e = t & 31, d0 = (t >> 5)*4;
    float a0=0.f, a1=0.f, a2=0.f, a3=0.f;
    for (int m = 0; m < Mm; m++){
        float te = T[m*32 + e];
        a0 = fmaf(T[m*32 + d0+0], te, a0);
        a1 = fmaf(T[m*32 + d0+1], te, a1);
        a2 = fmaf(T[m*32 + d0+2], te, a2);
        a3 = fmaf(T[m*32 + d0+3], te, a3);
    }
    float* vp = out_var + (size_t)n*Dd*Dd;
    vp[(d0+0)*32 + e] = a0 + ((d0+0)==e ? invb : 0.f);
    vp[(d0+1)*32 + e] = a1 + ((d0+1)==e ? invb : 0.f);
    vp[(d0+2)*32 + e] = a2 + ((d0+2)==e ? invb : 0.f);
    vp[(d0+3)*32 + e] = a3 + ((d0+3)==e ? invb : 0.f);
}

// ---------------- final scalar reduction -> lml ----------------
__global__ void reduce_lml_kernel(float* __restrict__ out_lml,
                                  const float* __restrict__ var_p,
                                  const float* __restrict__ beta_p,
                                  const float* __restrict__ qs)
{
    __shared__ double red[256];
    int t = threadIdx.x;
    double a1=0, a2=0, a3=0, a4=0, a5=0, a6=0;
    for (int i = t; i < Mm*Mm; i += 256){
        double kv = g_Kinv[i], uu = g_uuT[i];
        a1 += kv*(double)g_psi2[i];
        a2 += kv*uu;
        a3 += (double)g_KPK[i]*uu;
        a4 += (double)g_G[i]*uu;
    }
    for (int i = t; i < Mm; i += 256) a5 += log((double)g_Lp[off(i)+i]);
    for (int i = t; i < Mm*Dd; i += 256){
        int mm = i/Dd, dd = i%Dd;
        double x = (double)qs[(size_t)mm*Mm*Dd + (size_t)mm*Dd + dd];
        a6 += log(x*x);
    }
    double sums[6] = {a1,a2,a3,a4,a5,a6};
    double res[6];
    for (int s = 0; s < 6; s++){
        red[t] = sums[s];
        __syncthreads();
        for (int w = 128; w > 0; w >>= 1){
            if (t < w) red[t] += red[t+w];
            __syncthreads();
        }
        res[s] = red[0];
        __syncthreads();
    }
    if (t == 0){
        double variance = var_p[0], beta = beta_p[0];
        double psi0 = (double)Nn*variance;
        double lml = -0.5*beta*(double)Dd*(psi0 - res[0]);
        double logdetK = 2.0*res[4];
        double kl = 0.5*(res[1] - (double)(Mm*Dd) + (double)Dd*logdetK - res[5]);
        lml -= kl;
        lml -= 0.5*beta*(res[2] - res[3]);
        out_lml[0] = (float)lml;
    }
}

// ---------------- host launcher ----------------
extern "C" void kernel_launch(void* const* d_in, const int* in_sizes, int n_in,
                              void* d_out, int out_size)
{
    const float* Xmean = (const float*)d_in[0];
    const float* Xvar  = (const float*)d_in[1];
    const float* Z     = (const float*)d_in[2];
    const float* qmu   = (const float*)d_in[3];
    const float* qs    = (const float*)d_in[4];
    const float* ls    = (const float*)d_in[5];
    const float* var_p = (const float*)d_in[6];
    const float* beta_p= (const float*)d_in[7];

    float* out      = (float*)d_out;
    float* out_mean = out;                       // N*D
    float* out_var  = out + Nn*Dd;               // N*D*D
    float* out_lml  = out + Nn*Dd + (size_t)Nn*Dd*Dd; // 1

    float *pPsi1, *pKinv, *pA1, *pR, *puuT, *puuTp, *pGp, *pP2, *pKPK, *pG, *pTmpF, *pPsi2, *pLinv;
    cudaGetSymbolAddress((void**)&pPsi1, g_psi1);
    cudaGetSymbolAddress((void**)&pKinv, g_Kinv);
    cudaGetSymbolAddress((void**)&pA1,   g_A1);
    cudaGetSymbolAddress((void**)&pR,    g_R);
    cudaGetSymbolAddress((void**)&puuT,  g_uuT);
    cudaGetSymbolAddress((void**)&puuTp, g_uuTp);
    cudaGetSymbolAddress((void**)&pGp,   g_Gp);
    cudaGetSymbolAddress((void**)&pP2,   g_P2);
    cudaGetSymbolAddress((void**)&pKPK,  g_KPK);
    cudaGetSymbolAddress((void**)&pG,    g_G);
    cudaGetSymbolAddress((void**)&pTmpF, g_tmpF);
    cudaGetSymbolAddress((void**)&pPsi2, g_psi2);
    cudaGetSymbolAddress((void**)&pLinv, g_Linv);

    const int CHOL_SMEM = TRI*4;                 // 131584
    const int TRIS_SMEM = TRI*4 + Mm*33*4;       // 165376
    cudaFuncSetAttribute(cholesky_kernel, cudaFuncAttributeMaxDynamicSharedMemorySize, CHOL_SMEM);
    cudaFuncSetAttribute(trisolve_kernel, cudaFuncAttributeMaxDynamicSharedMemorySize, TRIS_SMEM);

    // 1. per-n prep
    prep_n_kernel<<<(Nn+255)/256, 256>>>(Xmean, Xvar, ls);
    // 2. qmk + Kmm
    prep_kmm_kernel<<<(Mm*Mm+255)/256, 256>>>(Z, ls, var_p);
    // 3. E2 precompute + psi1
    {
        dim3 b(32,8), g(Mm/32, Nn/8);
        e2_kernel<<<g, b>>>(Z);
        psi1_kernel<<<g, b>>>(Z, var_p);
    }
    // 4. psi2 (upper tile-triangle, 4 N-chunks) + combine/mirror
    {
        dim3 b(16,16), g(136, 4);
        psi2_kernel<<<g, b>>>(Z);
        psi2_combine_kernel<<<(Mm*Mm+255)/256, 256>>>(var_p);
    }
    // 5. Cholesky (smem-resident)
    cholesky_kernel<<<1, 256, CHOL_SMEM>>>();
    // 6. Linv (smem-resident)
    trisolve_kernel<<<Mm/32, 256, TRIS_SMEM>>>();
    // 7. Kinv = Linv^T Linv
    {
        dim3 g((Mm+63)/64, (Mm+63)/64);
        sgemm<1,0><<<g, 256>>>(Mm, Mm, Mm, pLinv, Mm, pLinv, Mm, pKinv, Mm, 1.f, 0.f);
    }
    // 8. masked R
    maskR_kernel<<<(Mm*Mm*Dd+255)/256, 256>>>(qs);
    // 9. uuT = qmu qmu^T + R R^T (split-K 16)
    {
        dim3 g((Mm+63)/64, (Mm+63)/64);
        sgemm<0,1><<<g, 256>>>(Mm, Mm, Dd, qmu, Dd, qmu, Dd, puuT, Mm, 1.f, 0.f);
        dim3 g2(Mm/128, Mm/128, 16);
        sgemm128<0,1><<<g2, 256>>>(Mm, Mm, Mm*Dd, (Mm*Dd)/16, pR, Mm*Dd, pR, Mm*Dd,
                                   puuTp, Mm, (size_t)Mm*Mm);
        reduce_parts_kernel<<<(Mm*Mm+255)/256, 256>>>(puuT, puuTp, 16, Mm*Mm, 1);
    }
    // 10. A1 = psi1 @ Kinv
    {
        dim3 g((Mm+63)/64, (Nn+63)/64);
        sgemm<0,0><<<g, 256>>>(Nn, Mm, Mm, pPsi1, Mm, pKinv, Mm, pA1, Mm, 1.f, 0.f);
    }
    // 11. forward_mean = A1 @ qmu
    {
        dim3 g((Dd+63)/64, (Nn+63)/64);
        sgemm<0,0><<<g, 256>>>(Nn, Dd, Mm, pA1, Mm, qmu, Dd, out_mean, Dd, 1.f, 0.f);
    }
    // 12. P2 = Kinv @ psi2 ; KPK = P2 @ Kinv
    {
        dim3 g((Mm+63)/64, (Mm+63)/64);
        sgemm<0,0><<<g, 256>>>(Mm, Mm, Mm, pKinv, Mm, pPsi2, Mm, pP2, Mm, 1.f, 0.f);
        sgemm<0,0><<<g, 256>>>(Mm, Mm, Mm, pP2, Mm, pKinv, Mm, pKPK, Mm, 1.f, 0.f);
    }
    // 13. G = A1^T A1 (split-K 8)
    {
        dim3 g(Mm/128, Mm/128, 8);
        sgemm128<1,0><<<g, 256>>>(Mm, Mm, Nn, Nn/8, pA1, Mm, pA1, Mm,
                                  pGp, Mm, (size_t)Mm*Mm);
        reduce_parts_kernel<<<(Mm*Mm+255)/256, 256>>>(pG, pGp, 8, Mm*Mm, 0);
    }
    // 14. tmpF = A1 @ R   (1024 x 8192, K=256)
    {
        dim3 g((Mm*Dd)/128, Nn/128, 1);
        sgemm128<0,0><<<g, 256>>>(Nn, Mm*Dd, Mm, Mm, pA1, Mm, pR, Mm*Dd,
                                  pTmpF, Mm*Dd, 0);
    }
    // 15. forward_var = batched T^T T + I/beta
    var_kernel<<<Nn, 256>>>(out_var, beta_p);
    // 16. lml
    reduce_lml_kernel<<<1, 256>>>(out_lml, var_p, beta_p, qs);
}

// round 4
// speedup vs baseline: 3.0413x; 1.4685x over previous
#include <cuda_runtime.h>
#include <cuda_bf16.h>
#include <math.h>

#define Nn 1024
#define Qq 32
#define Mm 256
#define Dd 32
#define JITTER 1e-6f
#define TRI (Mm*(Mm+1)/2)   // 32896 packed lower-tri elems

__device__ __forceinline__ int off(int i){ return (i*(i+1))>>1; }

// ---------------- scratch (device globals; no allocation) ----------------
__device__ float g_hw1[Nn*Qq];       // 0.5*w1
__device__ float g_wm1[Nn*Qq];       // w1*mu
__device__ float g_hw2[Nn*Qq];       // 0.5*w2
__device__ float g_w2[Nn*Qq];
__device__ float g_wm2[Nn*Qq];       // w2*mu
__device__ float g_G1[Nn];           // e1 - 0.5*A1sum
__device__ float g_F2[Nn];           // e2 - A2sum
__device__ float g_E2[Nn*Mm];        // B2 - 0.25*C2
__device__ float g_qmk[Mm*Mm];
__device__ float g_Kmm[Mm*Mm];
__device__ float g_Lp[TRI];          // packed lower-tri Cholesky factor
__device__ float g_Linv[Mm*Mm];
__device__ float g_Kinv[Mm*Mm];
__device__ float g_psi1[Nn*Mm];
__device__ float g_psi2[Mm*Mm];
__device__ float g_psi2p[8*Mm*Mm];   // 8 N-chunk partials
__device__ float g_A1[Nn*Mm];
__device__ float g_R[Mm*Mm*Dd];      // 8 MB masked q_sqrt
__device__ float g_uuT[Mm*Mm];
__device__ float g_uuTp[16*Mm*Mm];   // split-K partials
__device__ float g_Gp[8*Mm*Mm];      // split-K partials
__device__ float g_P2[Mm*Mm];
__device__ float g_KPK[Mm*Mm];
__device__ float g_G[Mm*Mm];
__device__ float g_tmpF[(size_t)Nn*Mm*Dd]; // 32 MB

// ---------------- per-n prep ----------------
__global__ void prep_n_kernel(const float* __restrict__ Xmean,
                              const float* __restrict__ Xvar,
                              const float* __restrict__ ls)
{
    int n = blockIdx.x*blockDim.x + threadIdx.x;
    if (n >= Nn) return;
    float ld1 = 0.f, ld2 = 0.f, a1 = 0.f, a2 = 0.f;
    #pragma unroll
    for (int q = 0; q < Qq; q++){
        float l = ls[q];
        float l2 = l*l;
        float S = Xvar[n*Qq+q];
        float mu = Xmean[n*Qq+q];
        float d1 = l2 + S;
        float d2 = l2 + 2.f*S;
        float w1 = 1.f/d1;
        float w2 = 1.f/d2;
        g_hw1[n*Qq+q] = 0.5f*w1;
        g_hw2[n*Qq+q] = 0.5f*w2;
        g_w2[n*Qq+q]  = w2;
        g_wm1[n*Qq+q] = w1*mu;
        g_wm2[n*Qq+q] = w2*mu;
        ld1 += logf(d1/l2);
        ld2 += logf(d2/l2);
        a1 = fmaf(w1*mu, mu, a1);
        a2 = fmaf(w2*mu, mu, a2);
    }
    g_G1[n] = -0.5f*ld1 - 0.5f*a1;
    g_F2[n] = -0.5f*ld2 - a2;
}

// ---------------- qmk and Kmm ----------------
__global__ void prep_kmm_kernel(const float* __restrict__ Z,
                                const float* __restrict__ ls,
                                const float* __restrict__ var_p)
{
    int idx = blockIdx.x*blockDim.x + threadIdx.x;
    if (idx >= Mm*Mm) return;
    int m = idx / Mm, k = idx % Mm;
    float s = 0.f;
    #pragma unroll
    for (int q = 0; q < Qq; q++){
        float l = ls[q];
        float d = Z[m*Qq+q] - Z[k*Qq+q];
        s += (d*d)/(l*l);
    }
    g_qmk[idx] = s;
    float v = var_p[0];
    g_Kmm[idx] = v*expf(-0.5f*s) + ((m==k)?JITTER:0.f);
}

// ---------------- E2[n,m] = sum_q Z*(wm2 - 0.25*w2*Z) ----------------
__global__ void e2_kernel(const float* __restrict__ Z)
{
    int tx = threadIdx.x, ty = threadIdx.y;
    int m = blockIdx.x*32 + tx;
    int n0 = blockIdx.y*8;
    int n = n0 + ty;
    __shared__ float Zs[32][33];
    __shared__ float wb[8][32], wmb[8][32];
    int t = ty*32 + tx;
    for (int i = t; i < 32*Qq; i += 256){
        int r = i/Qq, q = i%Qq;
        Zs[r][q] = Z[(blockIdx.x*32+r)*Qq + q];
    }
    for (int i = t; i < 8*Qq; i += 256){
        int r = i/Qq, q = i%Qq;
        wb[r][q]  = g_w2[(n0+r)*Qq + q];
        wmb[r][q] = g_wm2[(n0+r)*Qq + q];
    }
    __syncthreads();
    float s = 0.f;
    #pragma unroll
    for (int q = 0; q < Qq; q++){
        float z = Zs[tx][q];
        float tmp = fmaf(-0.25f*wb[ty][q], z, wmb[ty][q]);
        s = fmaf(tmp, z, s);
    }
    g_E2[n*Mm + m] = s;
}

// ---------------- psi1 = var*exp(G1[n] + sum_q Z*(wm1 - hw1*Z)) ----------------
__global__ void psi1_kernel(const float* __restrict__ Z,
                            const float* __restrict__ var_p)
{
    int tx = threadIdx.x, ty = threadIdx.y;
    int m = blockIdx.x*32 + tx;
    int n0 = blockIdx.y*8;
    int n = n0 + ty;
    __shared__ float Zs[32][33];
    __shared__ float wb[8][32], wmb[8][32], gs[8];
    int t = ty*32 + tx;
    for (int i = t; i < 32*Qq; i += 256){
        int r = i/Qq, q = i%Qq;
        Zs[r][q] = Z[(blockIdx.x*32+r)*Qq + q];
    }
    for (int i = t; i < 8*Qq; i += 256){
        int r = i/Qq, q = i%Qq;
        wb[r][q]  = g_hw1[(n0+r)*Qq + q];
        wmb[r][q] = g_wm1[(n0+r)*Qq + q];
    }
    if (t < 8) gs[t] = g_G1[n0+t];
    __syncthreads();
    float s = 0.f;
    #pragma unroll
    for (int q = 0; q < Qq; q++){
        float z = Zs[tx][q];
        float tmp = fmaf(-wb[ty][q], z, wmb[ty][q]);
        s = fmaf(tmp, z, s);
    }
    g_psi1[n*Mm + m] = var_p[0]*__expf(gs[ty] + s);
}

// ---------------- psi2 (upper tile-triangle, N split in 8 chunks) ----------------
__global__ void psi2_kernel(const float* __restrict__ Z)
{
    int rem = blockIdx.x, bi = 0;
    for (bi = 0; bi < 16; bi++){ int len = 16-bi; if (rem < len) break; rem -= len; }
    int bj = bi + rem;
    int chunk = blockIdx.y;
    int tx = threadIdx.x, ty = threadIdx.y;
    int m = bi*16 + ty;
    int k = bj*16 + tx;
    int t = ty*16 + tx;

    __shared__ float Zm[16][33], Zk[16][33];
    for (int i = t; i < 16*Qq; i += 256){
        int r = i/Qq, q = i%Qq;
        Zm[r][q] = Z[(bi*16+r)*Qq + q];
        Zk[r][q] = Z[(bj*16+r)*Qq + q];
    }
    __syncthreads();
    float zp[Qq];
    #pragma unroll
    for (int q = 0; q < Qq; q++) zp[q] = Zm[ty][q]*Zk[tx][q];
    float base = -0.25f*g_qmk[m*Mm + k];

    __shared__ float wb[16][33], F2s[16];
    __shared__ float Em[16][17], Ek[16][17];
    float acc = 0.f;
    int nbeg = chunk*(Nn/8), nend = nbeg + Nn/8;
    for (int n0 = nbeg; n0 < nend; n0 += 16){
        __syncthreads();
        for (int i = t; i < 16*Qq; i += 256){
            int r = i/Qq, q = i%Qq;
            wb[r][q] = g_hw2[(n0+r)*Qq + q];
        }
        {
            int nn = t >> 4, r = t & 15;
            Em[nn][r] = g_E2[(n0+nn)*Mm + bi*16 + r];
            Ek[nn][r] = g_E2[(n0+nn)*Mm + bj*16 + r];
        }
        if (t < 16) F2s[t] = g_F2[n0+t];
        __syncthreads();
        #pragma unroll 2
        for (int nn = 0; nn < 16; nn++){
            float dot = 0.f;
            #pragma unroll
            for (int q = 0; q < Qq; q++)
                dot = fmaf(wb[nn][q], zp[q], dot);
            float e = base + F2s[nn] + Em[nn][ty] + Ek[nn][tx] - dot;
            acc += __expf(e);
        }
    }
    g_psi2p[chunk*(Mm*Mm) + m*Mm + k] = acc;
}

// combine 8 partials, apply var^2, mirror lower tiles
__global__ void psi2_combine_kernel(const float* __restrict__ var_p)
{
    int idx = blockIdx.x*blockDim.x + threadIdx.x;
    if (idx >= Mm*Mm) return;
    int m = idx / Mm, k = idx % Mm;
    int src = ((m>>4) <= (k>>4)) ? (m*Mm + k) : (k*Mm + m);
    float s = 0.f;
    #pragma unroll
    for (int c = 0; c < 8; c++) s += g_psi2p[c*(Mm*Mm) + src];
    float v = var_p[0];
    g_psi2[idx] = v*v*s;
}

// ---------------- rank-2 Cholesky of Kmm (single block, packed smem) ----------------
__global__ void cholesky_kernel()
{
    extern __shared__ float sL[];      // TRI floats
    __shared__ float col1[Mm], col2[Mm];
    int t = threadIdx.x;
    for (int i = 0; i < Mm; i++)
        for (int j = t; j <= i; j += 256)
            sL[off(i)+j] = g_Kmm[i*Mm+j];
    __syncthreads();
    int rl = t>>3, cl = t&7;
    for (int k = 0; k < Mm; k += 2){
        // column k
        if (t == 0) sL[off(k)+k] = sqrtf(sL[off(k)+k]);
        __syncthreads();
        float invk = 1.f/sL[off(k)+k];
        float v1 = 0.f;
        if (t > k){ v1 = sL[off(t)+k]*invk; sL[off(t)+k] = v1; }
        col1[t] = v1;
        __syncthreads();
        // column k+1: subtract col k's rank-1, take diag sqrt
        float tmp = 0.f;
        if (t >= k+1) tmp = sL[off(t)+(k+1)] - col1[t]*col1[k+1];
        if (t == k+1) sL[off(k+1)+(k+1)] = sqrtf(tmp);
        __syncthreads();
        float inv2 = 1.f/sL[off(k+1)+(k+1)];
        float v2 = 0.f;
        if (t > k+1){ v2 = tmp*inv2; sL[off(t)+(k+1)] = v2; }
        col2[t] = v2;
        __syncthreads();
        // rank-2 trailing update on j >= k+2
        for (int i = k+2+rl; i < Mm; i += 32){
            float ci1 = col1[i], ci2 = col2[i];
            int b = off(i);
            for (int j = k+2+cl; j <= i; j += 8)
                sL[b+j] -= ci1*col1[j] + ci2*col2[j];
        }
        __syncthreads();
    }
    for (int i = 0; i < Mm; i++)
        for (int j = t; j <= i; j += 256)
            g_Lp[off(i)+j] = sL[off(i)+j];
}

// ---------------- Linv = L^{-1}: forward substitution, L + X both in smem ----------------
__global__ void trisolve_kernel()
{
    extern __shared__ float sm[];      // sLp[TRI] + Xs[256*33]
    float* sLp = sm;
    float* Xs  = sm + TRI;
    int c0 = blockIdx.x*32;
    int t = threadIdx.x;
    for (int i = t; i < TRI; i += 256) sLp[i] = g_Lp[i];
    for (int i = t; i < Mm*33; i += 256) Xs[i] = 0.f;
    __syncthreads();
    if (t < 32) Xs[(c0+t)*33 + t] = 1.f;
    __syncthreads();
    int c = t&31, ro = t>>5;
    for (int j = c0; j < Mm; j++){
        if (t < 32) Xs[j*33+t] *= (1.f/sLp[off(j)+j]);
        __syncthreads();
        float xjc = Xs[j*33+c];
        for (int i = j+1+ro; i < Mm; i += 8)
            Xs[i*33+c] -= sLp[off(i)+j]*xjc;
        __syncthreads();
    }
    for (int i = t; i < Mm*32; i += 256){
        int r = i>>5, cc = i&31;
        g_Linv[r*Mm + c0 + cc] = Xs[r*33+cc];
    }
}

// ---------------- masked R from q_sqrt ----------------
__global__ void maskR_kernel(const float* __restrict__ qs)
{
    int idx = blockIdx.x*blockDim.x + threadIdx.x;
    if (idx >= Mm*Mm*Dd) return;
    int a = idx / (Mm*Dd);
    int b = (idx / Dd) % Mm;
    g_R[idx] = (b <= a) ? qs[idx] : 0.f;
}

// ---------------- 64x64 SGEMM (small matrices) ----------------
template<int TA, int TB>
__global__ void sgemm(int M_, int N_, int K_,
                      const float* __restrict__ A, int lda,
                      const float* __restrict__ B, int ldb,
                      float* __restrict__ C, int ldc,
                      float alpha, float beta)
{
    const int BM = 64, BN = 64, BK = 16;
    __shared__ float As[BK][BM+1];
    __shared__ float Bs[BK][BN+1];
    int bm = blockIdx.y*BM, bn = blockIdx.x*BN;
    int tid = threadIdx.x;
    int tm = (tid/16)*4, tn = (tid%16)*4;
    float acc[4][4] = {};
    for (int k0 = 0; k0 < K_; k0 += BK){
        if (!TA){
            for (int i = tid; i < BM*BK; i += 256){
                int kk = i%BK, mm = i/BK;
                int gm = bm+mm, gk = k0+kk;
                As[kk][mm] = (gm < M_ && gk < K_) ? A[(size_t)gm*lda + gk] : 0.f;
            }
        } else {
            for (int i = tid; i < BM*BK; i += 256){
                int mm = i%BM, kk = i/BM;
                int gm = bm+mm, gk = k0+kk;
                As[kk][mm] = (gm < M_ && gk < K_) ? A[(size_t)gk*lda + gm] : 0.f;
            }
        }
        if (!TB){
            for (int i = tid; i < BN*BK; i += 256){
                int nn = i%BN, kk = i/BN;
                int gn = bn+nn, gk = k0+kk;
                Bs[kk][nn] = (gn < N_ && gk < K_) ? B[(size_t)gk*ldb + gn] : 0.f;
            }
        } else {
            for (int i = tid; i < BN*BK; i += 256){
                int kk = i%BK, nn = i/BK;
                int gn = bn+nn, gk = k0+kk;
                Bs[kk][nn] = (gn < N_ && gk < K_) ? B[(size_t)gn*ldb + gk] : 0.f;
            }
        }
        __syncthreads();
        #pragma unroll
        for (int kk = 0; kk < BK; kk++){
            float ra[4], rb[4];
            #pragma unroll
            for (int i = 0; i < 4; i++){ ra[i] = As[kk][tm+i]; rb[i] = Bs[kk][tn+i]; }
            #pragma unroll
            for (int i = 0; i < 4; i++)
                #pragma unroll
                for (int j = 0; j < 4; j++)
                    acc[i][j] = fmaf(ra[i], rb[j], acc[i][j]);
        }
        __syncthreads();
    }
    #pragma unroll
    for (int i = 0; i < 4; i++){
        int gm = bm + tm + i;
        if (gm >= M_) continue;
        #pragma unroll
        for (int j = 0; j < 4; j++){
            int gn = bn + tn + j;
            if (gn >= N_) continue;
            float prev = (beta != 0.f) ? C[(size_t)gm*ldc + gn] : 0.f;
            C[(size_t)gm*ldc + gn] = alpha*acc[i][j] + beta*prev;
        }
    }
}

// ---------------- 128x128 SGEMM, 8x8/thread, optional split-K via blockIdx.z ----------------
template<int TA, int TB>
__global__ void sgemm128(int M_, int N_, int K_, int Kchunk,
                         const float* __restrict__ A, int lda,
                         const float* __restrict__ B, int ldb,
                         float* __restrict__ C, int ldc, size_t partStride)
{
    const int BM = 128, BN = 128, BK = 16;
    __shared__ float As[BK][BM+4];
    __shared__ float Bs[BK][BN+4];
    int bm = blockIdx.y*BM, bn = blockIdx.x*BN;
    int kbeg = blockIdx.z*Kchunk;
    int kend = kbeg + Kchunk; if (kend > K_) kend = K_;
    float* Cb = C + (size_t)blockIdx.z*partStride;
    int tid = threadIdx.x;
    int tm = (tid/16)*8, tn = (tid%16)*8;
    float acc[8][8] = {};
    for (int k0 = kbeg; k0 < kend; k0 += BK){
        if (!TA){
            #pragma unroll
            for (int i = tid; i < BM*BK; i += 256){
                int kk = i%BK, mm = i/BK;
                As[kk][mm] = A[(size_t)(bm+mm)*lda + (k0+kk)];
            }
        } else {
            #pragma unroll
            for (int i = tid; i < BM*BK; i += 256){
                int mm = i%BM, kk = i/BM;
                As[kk][mm] = A[(size_t)(k0+kk)*lda + (bm+mm)];
            }
        }
        if (!TB){
            #pragma unroll
            for (int i = tid; i < BN*BK; i += 256){
                int nn = i%BN, kk = i/BN;
                Bs[kk][nn] = B[(size_t)(k0+kk)*ldb + (bn+nn)];
            }
        } else {
            #pragma unroll
            for (int i = tid; i < BN*BK; i += 256){
                int kk = i%BK, nn = i/BK;
                Bs[kk][nn] = B[(size_t)(bn+nn)*ldb + (k0+kk)];
            }
        }
        __syncthreads();
        #pragma unroll
        for (int kk = 0; kk < BK; kk++){
            float ra[8], rb[8];
            *(float4*)&ra[0] = *(const float4*)&As[kk][tm];
            *(float4*)&ra[4] = *(const float4*)&As[kk][tm+4];
            *(float4*)&rb[0] = *(const float4*)&Bs[kk][tn];
            *(float4*)&rb[4] = *(const float4*)&Bs[kk][tn+4];
            #pragma unroll
            for (int i = 0; i < 8; i++)
                #pragma unroll
                for (int j = 0; j < 8; j++)
                    acc[i][j] = fmaf(ra[i], rb[j], acc[i][j]);
        }
        __syncthreads();
    }
    #pragma unroll
    for (int i = 0; i < 8; i++){
        float* cp = Cb + (size_t)(bm+tm+i)*ldc + bn + tn;
        *(float4*)cp       = *(float4*)&acc[i][0];
        *(float4*)(cp + 4) = *(float4*)&acc[i][4];
    }
}

// ---------------- sum split-K partials into out ----------------
__global__ void reduce_parts_kernel(float* __restrict__ out,
                                    const float* __restrict__ parts,
                                    int S, int MN, int addBase)
{
    int idx = blockIdx.x*blockDim.x + threadIdx.x;
    if (idx >= MN) return;
    float s = addBase ? out[idx] : 0.f;
    for (int i = 0; i < S; i++) s += parts[(size_t)i*MN + idx];
    out[idx] = s;
}

// ---------------- batched SYRK for forward_var ----------------
__global__ void var_kernel(float* __restrict__ out_var, const float* __restrict__ beta_p)
{
    __shared__ float T[Mm*Dd]; // 32 KB
    int n = blockIdx.x;
    int t = threadIdx.x;
    for (int i = t; i < Mm*Dd; i += 256) T[i] = g_tmpF[(size_t)n*(Mm*Dd) + i];
    __syncthreads();
    float invb = 1.f/beta_p[0];
    int e = t & 31, d0 = (t >> 5)*4;
    float a0=0.f, a1=0.f, a2=0.f, a3=0.f;
    for (int m = 0; m < Mm; m++){
        float te = T[m*32 + e];
        a0 = fmaf(T[m*32 + d0+0], te, a0);
        a1 = fmaf(T[m*32 + d0+1], te, a1);
        a2 = fmaf(T[m*32 + d0+2], te, a2);
        a3 = fmaf(T[m*32 + d0+3], te, a3);
    }
    float* vp = out_var + (size_t)n*Dd*Dd;
    vp[(d0+0)*32 + e] = a0 + ((d0+0)==e ? invb : 0.f);
    vp[(d0+1)*32 + e] = a1 + ((d0+1)==e ? invb : 0.f);
    vp[(d0+2)*32 + e] = a2 + ((d0+2)==e ? invb : 0.f);
    vp[(d0+3)*32 + e] = a3 + ((d0+3)==e ? invb : 0.f);
}

// ---------------- final scalar reduction -> lml ----------------
__global__ void reduce_lml_kernel(float* __restrict__ out_lml,
                                  const float* __restrict__ var_p,
                                  const float* __restrict__ beta_p,
                                  const float* __restrict__ qs)
{
    __shared__ double red[256];
    int t = threadIdx.x;
    double a1=0, a2=0, a3=0, a4=0, a5=0, a6=0;
    for (int i = t; i < Mm*Mm; i += 256){
        double kv = g_Kinv[i], uu = g_uuT[i];
        a1 += kv*(double)g_psi2[i];
        a2 += kv*uu;
        a3 += (double)g_KPK[i]*uu;
        a4 += (double)g_G[i]*uu;
    }
    for (int i = t; i < Mm; i += 256) a5 += log((double)g_Lp[off(i)+i]);
    for (int i = t; i < Mm*Dd; i += 256){
        int mm = i/Dd, dd = i%Dd;
        double x = (double)qs[(size_t)mm*Mm*Dd + (size_t)mm*Dd + dd];
        a6 += log(x*x);
    }
    double sums[6] = {a1,a2,a3,a4,a5,a6};
    double res[6];
    for (int s = 0; s < 6; s++){
        red[t] = sums[s];
        __syncthreads();
        for (int w = 128; w > 0; w >>= 1){
            if (t < w) red[t] += red[t+w];
            __syncthreads();
        }
        res[s] = red[0];
        __syncthreads();
    }
    if (t == 0){
        double variance = var_p[0], beta = beta_p[0];
        double psi0 = (double)Nn*variance;
        double lml = -0.5*beta*(double)Dd*(psi0 - res[0]);
        double logdetK = 2.0*res[4];
        double kl = 0.5*(res[1] - (double)(Mm*Dd) + (double)Dd*logdetK - res[5]);
        lml -= kl;
        lml -= 0.5*beta*(res[2] - res[3]);
        out_lml[0] = (float)lml;
    }
}

// ---------------- host launcher with fork/join stream overlap ----------------
extern "C" void kernel_launch(void* const* d_in, const int* in_sizes, int n_in,
                              void* d_out, int out_size)
{
    const float* Xmean = (const float*)d_in[0];
    const float* Xvar  = (const float*)d_in[1];
    const float* Z     = (const float*)d_in[2];
    const float* qmu   = (const float*)d_in[3];
    const float* qs    = (const float*)d_in[4];
    const float* ls    = (const float*)d_in[5];
    const float* var_p = (const float*)d_in[6];
    const float* beta_p= (const float*)d_in[7];

    float* out      = (float*)d_out;
    float* out_mean = out;                       // N*D
    float* out_var  = out + Nn*Dd;               // N*D*D
    float* out_lml  = out + Nn*Dd + (size_t)Nn*Dd*Dd; // 1

    float *pPsi1, *pKinv, *pA1, *pR, *puuT, *puuTp, *pGp, *pP2, *pKPK, *pG, *pTmpF, *pPsi2, *pLinv;
    cudaGetSymbolAddress((void**)&pPsi1, g_psi1);
    cudaGetSymbolAddress((void**)&pKinv, g_Kinv);
    cudaGetSymbolAddress((void**)&pA1,   g_A1);
    cudaGetSymbolAddress((void**)&pR,    g_R);
    cudaGetSymbolAddress((void**)&puuT,  g_uuT);
    cudaGetSymbolAddress((void**)&puuTp, g_uuTp);
    cudaGetSymbolAddress((void**)&pGp,   g_Gp);
    cudaGetSymbolAddress((void**)&pP2,   g_P2);
    cudaGetSymbolAddress((void**)&pKPK,  g_KPK);
    cudaGetSymbolAddress((void**)&pG,    g_G);
    cudaGetSymbolAddress((void**)&pTmpF, g_tmpF);
    cudaGetSymbolAddress((void**)&pPsi2, g_psi2);
    cudaGetSymbolAddress((void**)&pLinv, g_Linv);

    const int CHOL_SMEM = TRI*4;                 // 131584
    const int TRIS_SMEM = TRI*4 + Mm*33*4;       // 165376
    cudaFuncSetAttribute(cholesky_kernel, cudaFuncAttributeMaxDynamicSharedMemorySize, CHOL_SMEM);
    cudaFuncSetAttribute(trisolve_kernel, cudaFuncAttributeMaxDynamicSharedMemorySize, TRIS_SMEM);

    // one-time host-side stream/event setup (no device memory involved)
    static cudaStream_t s1 = nullptr, s2 = nullptr;
    static cudaEvent_t e0 = nullptr, e1 = nullptr, e2 = nullptr, e3 = nullptr, e4 = nullptr;
    if (!s1){
        cudaStreamCreateWithFlags(&s1, cudaStreamNonBlocking);
        cudaStreamCreateWithFlags(&s2, cudaStreamNonBlocking);
        cudaEventCreateWithFlags(&e0, cudaEventDisableTiming);
        cudaEventCreateWithFlags(&e1, cudaEventDisableTiming);
        cudaEventCreateWithFlags(&e2, cudaEventDisableTiming);
        cudaEventCreateWithFlags(&e3, cudaEventDisableTiming);
        cudaEventCreateWithFlags(&e4, cudaEventDisableTiming);
    }

    // ---- common prep on origin stream ----
    prep_n_kernel<<<(Nn+255)/256, 256>>>(Xmean, Xvar, ls);
    prep_kmm_kernel<<<(Mm*Mm+255)/256, 256>>>(Z, ls, var_p);
    cudaEventRecord(e0, 0);

    // ---- branch s1: Cholesky chain ----
    cudaStreamWaitEvent(s1, e0, 0);
    cholesky_kernel<<<1, 256, CHOL_SMEM, s1>>>();
    trisolve_kernel<<<Mm/32, 256, TRIS_SMEM, s1>>>();
    {
        dim3 g((Mm+63)/64, (Mm+63)/64);
        sgemm<1,0><<<g, 256, 0, s1>>>(Mm, Mm, Mm, pLinv, Mm, pLinv, Mm, pKinv, Mm, 1.f, 0.f);
    }
    cudaEventRecord(e1, s1);

    // ---- branch s2: R / uuT chain ----
    cudaStreamWaitEvent(s2, e0, 0);
    maskR_kernel<<<(Mm*Mm*Dd+255)/256, 256, 0, s2>>>(qs);
    {
        dim3 g((Mm+63)/64, (Mm+63)/64);
        sgemm<0,1><<<g, 256, 0, s2>>>(Mm, Mm, Dd, qmu, Dd, qmu, Dd, puuT, Mm, 1.f, 0.f);
        dim3 g2(Mm/128, Mm/128, 16);
        sgemm128<0,1><<<g2, 256, 0, s2>>>(Mm, Mm, Mm*Dd, (Mm*Dd)/16, pR, Mm*Dd, pR, Mm*Dd,
                                          puuTp, Mm, (size_t)Mm*Mm);
        reduce_parts_kernel<<<(Mm*Mm+255)/256, 256, 0, s2>>>(puuT, puuTp, 16, Mm*Mm, 1);
    }
    cudaEventRecord(e2, s2);

    // ---- origin stream: psi chain (concurrent with s1, s2) ----
    {
        dim3 b(32,8), g(Mm/32, Nn/8);
        e2_kernel<<<g, b>>>(Z);
        psi1_kernel<<<g, b>>>(Z, var_p);
    }
    {
        dim3 b(16,16), g(136, 8);
        psi2_kernel<<<g, b>>>(Z);
        psi2_combine_kernel<<<(Mm*Mm+255)/256, 256>>>(var_p);
    }

    // ---- join Kinv, compute A1 ----
    cudaStreamWaitEvent(0, e1, 0);
    {
        dim3 g((Mm+63)/64, (Nn+63)/64);
        sgemm<0,0><<<g, 256>>>(Nn, Mm, Mm, pPsi1, Mm, pKinv, Mm, pA1, Mm, 1.f, 0.f);
    }
    cudaEventRecord(e3, 0);

    // ---- branch s1 (post-A1): mean, P2, KPK, G ----
    cudaStreamWaitEvent(s1, e3, 0);
    {
        dim3 g((Dd+63)/64, (Nn+63)/64);
        sgemm<0,0><<<g, 256, 0, s1>>>(Nn, Dd, Mm, pA1, Mm, qmu, Dd, out_mean, Dd, 1.f, 0.f);
    }
    {
        dim3 g((Mm+63)/64, (Mm+63)/64);
        sgemm<0,0><<<g, 256, 0, s1>>>(Mm, Mm, Mm, pKinv, Mm, pPsi2, Mm, pP2, Mm, 1.f, 0.f);
        sgemm<0,0><<<g, 256, 0, s1>>>(Mm, Mm, Mm, pP2, Mm, pKinv, Mm, pKPK, Mm, 1.f, 0.f);
    }
    {
        dim3 g(Mm/128, Mm/128, 8);
        sgemm128<1,0><<<g, 256, 0, s1>>>(Mm, Mm, Nn, Nn/8, pA1, Mm, pA1, Mm,
                                         pGp, Mm, (size_t)Mm*Mm);
        reduce_parts_kernel<<<(Mm*Mm+255)/256, 256, 0, s1>>>(pG, pGp, 8, Mm*Mm, 0);
    }
    cudaEventRecord(e4, s1);

    // ---- origin stream: tmpF -> var (needs R from s2) ----
    cudaStreamWaitEvent(0, e2, 0);
    {
        dim3 g((Mm*Dd)/128, Nn/128, 1);
        sgemm128<0,0><<<g, 256>>>(Nn, Mm*Dd, Mm, Mm, pA1, Mm, pR, Mm*Dd,
                                  pTmpF, Mm*Dd, 0);
    }
    var_kernel<<<Nn, 256>>>(out_var, beta_p);

    // ---- final join and lml ----
    cudaStreamWaitEvent(0, e4, 0);
    reduce_lml_kernel<<<1, 256>>>(out_lml, var_p, beta_p, qs);
}

// round 5
// speedup vs baseline: 3.8427x; 1.2635x over previous
#include <cuda_runtime.h>
#include <cuda_bf16.h>
#include <math.h>

#define Nn 1024
#define Qq 32
#define Mm 256
#define Dd 32
#define JITTER 1e-6f
#define TRI (Mm*(Mm+1)/2)   // 32896 packed lower-tri elems

__device__ __forceinline__ int off(int i){ return (i*(i+1))>>1; }

// ---------------- scratch (device globals; no allocation) ----------------
__device__ float g_hw1[Nn*Qq];
__device__ float g_wm1[Nn*Qq];
__device__ float g_hw2[Nn*Qq];
__device__ float g_w2[Nn*Qq];
__device__ float g_wm2[Nn*Qq];
__device__ float g_G1[Nn];
__device__ float g_F2[Nn];
__device__ float g_E2[Nn*Mm];
__device__ float g_qmk[Mm*Mm];
__device__ float g_Kmm[Mm*Mm];
__device__ float g_Lp[TRI];          // packed: after cholinv chain holds Linv
__device__ float g_Ldiag[Mm];        // diag of L (for logdet)
__device__ float g_T128[128*128];    // temp for level-3 combine
__device__ float g_Linv[Mm*Mm];
__device__ float g_Kinv[Mm*Mm];
__device__ float g_psi1[Nn*Mm];
__device__ float g_psi2[Mm*Mm];
__device__ float g_psi2p[8*Mm*Mm];
__device__ float g_A1[Nn*Mm];
__device__ float g_R[Mm*Mm*Dd];      // 8 MB masked q_sqrt
__device__ float g_uuT[Mm*Mm];
__device__ float g_uuTp[16*Mm*Mm];
__device__ float g_Gp[8*Mm*Mm];
__device__ float g_P2[Mm*Mm];
__device__ float g_KPK[Mm*Mm];
__device__ float g_G[Mm*Mm];
__device__ float g_tmpF[(size_t)Nn*Mm*Dd]; // 32 MB

// ---------------- per-n prep ----------------
__global__ void prep_n_kernel(const float* __restrict__ Xmean,
                              const float* __restrict__ Xvar,
                              const float* __restrict__ ls)
{
    int n = blockIdx.x*blockDim.x + threadIdx.x;
    if (n >= Nn) return;
    float ld1 = 0.f, ld2 = 0.f, a1 = 0.f, a2 = 0.f;
    #pragma unroll
    for (int q = 0; q < Qq; q++){
        float l = ls[q];
        float l2 = l*l;
        float S = Xvar[n*Qq+q];
        float mu = Xmean[n*Qq+q];
        float d1 = l2 + S;
        float d2 = l2 + 2.f*S;
        float w1 = 1.f/d1;
        float w2 = 1.f/d2;
        g_hw1[n*Qq+q] = 0.5f*w1;
        g_hw2[n*Qq+q] = 0.5f*w2;
        g_w2[n*Qq+q]  = w2;
        g_wm1[n*Qq+q] = w1*mu;
        g_wm2[n*Qq+q] = w2*mu;
        ld1 += logf(d1/l2);
        ld2 += logf(d2/l2);
        a1 = fmaf(w1*mu, mu, a1);
        a2 = fmaf(w2*mu, mu, a2);
    }
    g_G1[n] = -0.5f*ld1 - 0.5f*a1;
    g_F2[n] = -0.5f*ld2 - a2;
}

// ---------------- qmk and Kmm ----------------
__global__ void prep_kmm_kernel(const float* __restrict__ Z,
                                const float* __restrict__ ls,
                                const float* __restrict__ var_p)
{
    int idx = blockIdx.x*blockDim.x + threadIdx.x;
    if (idx >= Mm*Mm) return;
    int m = idx / Mm, k = idx % Mm;
    float s = 0.f;
    #pragma unroll
    for (int q = 0; q < Qq; q++){
        float l = ls[q];
        float d = Z[m*Qq+q] - Z[k*Qq+q];
        s += (d*d)/(l*l);
    }
    g_qmk[idx] = s;
    float v = var_p[0];
    g_Kmm[idx] = v*expf(-0.5f*s) + ((m==k)?JITTER:0.f);
}

// ---------------- E2 ----------------
__global__ void e2_kernel(const float* __restrict__ Z)
{
    int tx = threadIdx.x, ty = threadIdx.y;
    int m = blockIdx.x*32 + tx;
    int n0 = blockIdx.y*8;
    int n = n0 + ty;
    __shared__ float Zs[32][33];
    __shared__ float wb[8][32], wmb[8][32];
    int t = ty*32 + tx;
    for (int i = t; i < 32*Qq; i += 256){
        int r = i/Qq, q = i%Qq;
        Zs[r][q] = Z[(blockIdx.x*32+r)*Qq + q];
    }
    for (int i = t; i < 8*Qq; i += 256){
        int r = i/Qq, q = i%Qq;
        wb[r][q]  = g_w2[(n0+r)*Qq + q];
        wmb[r][q] = g_wm2[(n0+r)*Qq + q];
    }
    __syncthreads();
    float s = 0.f;
    #pragma unroll
    for (int q = 0; q < Qq; q++){
        float z = Zs[tx][q];
        float tmp = fmaf(-0.25f*wb[ty][q], z, wmb[ty][q]);
        s = fmaf(tmp, z, s);
    }
    g_E2[n*Mm + m] = s;
}

// ---------------- psi1 ----------------
__global__ void psi1_kernel(const float* __restrict__ Z,
                            const float* __restrict__ var_p)
{
    int tx = threadIdx.x, ty = threadIdx.y;
    int m = blockIdx.x*32 + tx;
    int n0 = blockIdx.y*8;
    int n = n0 + ty;
    __shared__ float Zs[32][33];
    __shared__ float wb[8][32], wmb[8][32], gs[8];
    int t = ty*32 + tx;
    for (int i = t; i < 32*Qq; i += 256){
        int r = i/Qq, q = i%Qq;
        Zs[r][q] = Z[(blockIdx.x*32+r)*Qq + q];
    }
    for (int i = t; i < 8*Qq; i += 256){
        int r = i/Qq, q = i%Qq;
        wb[r][q]  = g_hw1[(n0+r)*Qq + q];
        wmb[r][q] = g_wm1[(n0+r)*Qq + q];
    }
    if (t < 8) gs[t] = g_G1[n0+t];
    __syncthreads();
    float s = 0.f;
    #pragma unroll
    for (int q = 0; q < Qq; q++){
        float z = Zs[tx][q];
        float tmp = fmaf(-wb[ty][q], z, wmb[ty][q]);
        s = fmaf(tmp, z, s);
    }
    g_psi1[n*Mm + m] = var_p[0]*__expf(gs[ty] + s);
}

// ---------------- psi2 ----------------
__global__ void psi2_kernel(const float* __restrict__ Z)
{
    int rem = blockIdx.x, bi = 0;
    for (bi = 0; bi < 16; bi++){ int len = 16-bi; if (rem < len) break; rem -= len; }
    int bj = bi + rem;
    int chunk = blockIdx.y;
    int tx = threadIdx.x, ty = threadIdx.y;
    int m = bi*16 + ty;
    int k = bj*16 + tx;
    int t = ty*16 + tx;

    __shared__ float Zm[16][33], Zk[16][33];
    for (int i = t; i < 16*Qq; i += 256){
        int r = i/Qq, q = i%Qq;
        Zm[r][q] = Z[(bi*16+r)*Qq + q];
        Zk[r][q] = Z[(bj*16+r)*Qq + q];
    }
    __syncthreads();
    float zp[Qq];
    #pragma unroll
    for (int q = 0; q < Qq; q++) zp[q] = Zm[ty][q]*Zk[tx][q];
    float base = -0.25f*g_qmk[m*Mm + k];

    __shared__ float wb[16][33], F2s[16];
    __shared__ float Em[16][17], Ek[16][17];
    float acc = 0.f;
    int nbeg = chunk*(Nn/8), nend = nbeg + Nn/8;
    for (int n0 = nbeg; n0 < nend; n0 += 16){
        __syncthreads();
        for (int i = t; i < 16*Qq; i += 256){
            int r = i/Qq, q = i%Qq;
            wb[r][q] = g_hw2[(n0+r)*Qq + q];
        }
        {
            int nn = t >> 4, r = t & 15;
            Em[nn][r] = g_E2[(n0+nn)*Mm + bi*16 + r];
            Ek[nn][r] = g_E2[(n0+nn)*Mm + bj*16 + r];
        }
        if (t < 16) F2s[t] = g_F2[n0+t];
        __syncthreads();
        #pragma unroll 2
        for (int nn = 0; nn < 16; nn++){
            float dot = 0.f;
            #pragma unroll
            for (int q = 0; q < Qq; q++)
                dot = fmaf(wb[nn][q], zp[q], dot);
            float e = base + F2s[nn] + Em[nn][ty] + Ek[nn][tx] - dot;
            acc += __expf(e);
        }
    }
    g_psi2p[chunk*(Mm*Mm) + m*Mm + k] = acc;
}

__global__ void psi2_combine_kernel(const float* __restrict__ var_p)
{
    int idx = blockIdx.x*blockDim.x + threadIdx.x;
    if (idx >= Mm*Mm) return;
    int m = idx / Mm, k = idx % Mm;
    int src = ((m>>4) <= (k>>4)) ? (m*Mm + k) : (k*Mm + m);
    float s = 0.f;
    #pragma unroll
    for (int c = 0; c < 8; c++) s += g_psi2p[c*(Mm*Mm) + src];
    float v = var_p[0];
    g_psi2[idx] = v*v*s;
}

// ============ Kernel A: Cholesky + 32x32 diag inversion + level-1 combine ============
// 1 CTA, 1024 threads. Dyn smem: sL[TRI] + Vt[8*32*33]
__global__ void cholinv_kernel()
{
    extern __shared__ float sm[];
    float* sL = sm;            // TRI
    float* Vt = sm + TRI;      // 8448
    __shared__ float col1[Mm], col2[Mm];
    int t = threadIdx.x;
    int warp = t >> 5, lane = t & 31;

    // load packed lower triangle
    for (int idx = t; idx < TRI; idx += 1024){
        int i = (int)((sqrtf(8.f*(float)idx + 1.f) - 1.f)*0.5f);
        while (off(i+1) <= idx) i++;
        while (off(i) > idx) i--;
        int j = idx - off(i);
        sL[idx] = g_Kmm[i*Mm + j];
    }
    __syncthreads();

    // ---- rank-2 Cholesky (warp=row, lane=col mapping; conflict-free) ----
    for (int k = 0; k < Mm; k += 2){
        if (t == 0) sL[off(k)+k] = sqrtf(sL[off(k)+k]);
        __syncthreads();
        float invk = 1.f/sL[off(k)+k];
        float v1 = 0.f;
        if (t > k && t < Mm){ v1 = sL[off(t)+k]*invk; sL[off(t)+k] = v1; }
        if (t < Mm) col1[t] = v1;
        __syncthreads();
        float tmp = 0.f;
        if (t >= k+1 && t < Mm) tmp = sL[off(t)+(k+1)] - col1[t]*col1[k+1];
        if (t == k+1) sL[off(k+1)+(k+1)] = sqrtf(tmp);
        __syncthreads();
        float inv2 = 1.f/sL[off(k+1)+(k+1)];
        float v2 = 0.f;
        if (t > k+1 && t < Mm){ v2 = tmp*inv2; sL[off(t)+(k+1)] = v2; }
        if (t < Mm) col2[t] = v2;
        __syncthreads();
        for (int i = k+2+warp; i < Mm; i += 32){
            float ci1 = col1[i], ci2 = col2[i];
            int b = off(i);
            for (int j = k+2+lane; j <= i; j += 32)
                sL[b+j] -= ci1*col1[j] + ci2*col2[j];
        }
        __syncthreads();
    }
    // save diag of L for logdet
    if (t < Mm) g_Ldiag[t] = sL[off(t)+t];
    __syncthreads();

    // ---- invert 8 diagonal 32x32 blocks (warp w -> block w) ----
    if (warp < 8){
        int r0 = warp*32;
        float* V = Vt + warp*1056;      // 32x33
        int c = lane;
        for (int r = 0; r < 32; r++){
            float sum = 0.f;
            for (int k = c; k < r; k++)
                sum = fmaf(sL[off(r0+r)+r0+k], V[k*33+c], sum);
            float diag = sL[off(r0+r)+r0+r];
            float v;
            if (c < r)       v = -sum/diag;
            else if (c == r) v = 1.f/diag;
            else             v = 0.f;
            V[r*33+c] = v;
        }
    }
    __syncthreads();
    // copy inverted diag blocks back into sL
    {
        int pos = t & 1023;
        int r = pos >> 5, c = pos & 31;
        for (int b = 0; b < 8; b++)
            if (c <= r) sL[off(b*32+r)+b*32+c] = Vt[b*1056 + r*33 + c];
    }
    __syncthreads();

    // ---- level-1 combine: 4 pairs of 32-blocks -> inverted 64-blocks ----
    // pair p: rows [64p,64p+32)=A, [64p+32,64p+64)=C; O = -Cinv*B*Ainv
    {
        int p  = t >> 8;           // 0..3
        int ti = t & 255;
        int i  = ti >> 3;          // 0..31
        int j0 = (ti & 7)*4;       // 0..28
        int row0 = p*64;
        float acc[4] = {0,0,0,0};
        for (int k = 0; k < 32; k++){
            float b = sL[off(row0+32+i)+row0+k];
            #pragma unroll
            for (int jj = 0; jj < 4; jj++){
                int j = j0+jj;
                if (j <= k) acc[jj] = fmaf(b, sL[off(row0+k)+row0+j], acc[jj]);
            }
        }
        float* Tp = Vt + p*1056;
        #pragma unroll
        for (int jj = 0; jj < 4; jj++) Tp[i*33 + j0+jj] = acc[jj];
        __syncthreads();
        float acc2[4] = {0,0,0,0};
        for (int k = 0; k <= i; k++){
            float cv = sL[off(row0+32+i)+row0+32+k];
            #pragma unroll
            for (int jj = 0; jj < 4; jj++)
                acc2[jj] = fmaf(cv, Tp[k*33 + j0+jj], acc2[jj]);
        }
        #pragma unroll
        for (int jj = 0; jj < 4; jj++)
            sL[off(row0+32+i)+row0+j0+jj] = -acc2[jj];
    }
    __syncthreads();

    // store packed result
    for (int idx = t; idx < TRI; idx += 1024) g_Lp[idx] = sL[idx];
}

// ============ Kernel B: level-2 combine (64 -> 128), 2 CTAs x 256 thr ============
__global__ void inv_lvl2_kernel()
{
    __shared__ float Tt[64*65];
    int row0 = blockIdx.x*128;
    int ti = threadIdx.x;
    int i0 = (ti >> 4)*4;     // 0..60
    int j0 = (ti & 15)*4;     // 0..60
    float acc[4][4] = {};
    for (int k = 0; k < 64; k++){
        float b[4], a[4];
        #pragma unroll
        for (int ii = 0; ii < 4; ii++) b[ii] = g_Lp[off(row0+64+i0+ii)+row0+k];
        #pragma unroll
        for (int jj = 0; jj < 4; jj++){
            int j = j0+jj;
            a[jj] = (j <= k) ? g_Lp[off(row0+k)+row0+j] : 0.f;
        }
        #pragma unroll
        for (int ii = 0; ii < 4; ii++)
            #pragma unroll
            for (int jj = 0; jj < 4; jj++)
                acc[ii][jj] = fmaf(b[ii], a[jj], acc[ii][jj]);
    }
    #pragma unroll
    for (int ii = 0; ii < 4; ii++)
        #pragma unroll
        for (int jj = 0; jj < 4; jj++)
            Tt[(i0+ii)*65 + j0+jj] = acc[ii][jj];
    __syncthreads();
    float acc2[4][4] = {};
    for (int k = 0; k < 64; k++){
        float cv[4], tv[4];
        #pragma unroll
        for (int ii = 0; ii < 4; ii++){
            int i = i0+ii;
            cv[ii] = (k <= i) ? g_Lp[off(row0+64+i)+row0+64+k] : 0.f;
        }
        #pragma unroll
        for (int jj = 0; jj < 4; jj++) tv[jj] = Tt[k*65 + j0+jj];
        #pragma unroll
        for (int ii = 0; ii < 4; ii++)
            #pragma unroll
            for (int jj = 0; jj < 4; jj++)
                acc2[ii][jj] = fmaf(cv[ii], tv[jj], acc2[ii][jj]);
    }
    #pragma unroll
    for (int ii = 0; ii < 4; ii++)
        #pragma unroll
        for (int jj = 0; jj < 4; jj++)
            g_Lp[off(row0+64+i0+ii)+row0+j0+jj] = -acc2[ii][jj];
}

// ============ Kernel C1: level-3 T = B * Ainv(128), 4 CTAs x 256 thr ============
__global__ void inv_lvl3a_kernel()
{
    int ti = threadIdx.x;
    int i0 = blockIdx.x*32 + (ti >> 5)*4;   // 32-row slab
    int j0 = (ti & 31)*4;                    // 128 cols
    float acc[4][4] = {};
    for (int k = 0; k < 128; k++){
        float b[4], a[4];
        #pragma unroll
        for (int ii = 0; ii < 4; ii++) b[ii] = g_Lp[off(128+i0+ii)+k];
        #pragma unroll
        for (int jj = 0; jj < 4; jj++){
            int j = j0+jj;
            a[jj] = (j <= k) ? g_Lp[off(k)+j] : 0.f;
        }
        #pragma unroll
        for (int ii = 0; ii < 4; ii++)
            #pragma unroll
            for (int jj = 0; jj < 4; jj++)
                acc[ii][jj] = fmaf(b[ii], a[jj], acc[ii][jj]);
    }
    #pragma unroll
    for (int ii = 0; ii < 4; ii++)
        #pragma unroll
        for (int jj = 0; jj < 4; jj++)
            g_T128[(i0+ii)*128 + j0+jj] = acc[ii][jj];
}

// ============ Kernel C2: level-3 O = -Cinv(128) * T, 4 CTAs x 256 thr ============
__global__ void inv_lvl3b_kernel()
{
    int ti = threadIdx.x;
    int i0 = blockIdx.x*32 + (ti >> 5)*4;
    int j0 = (ti & 31)*4;
    float acc[4][4] = {};
    for (int k = 0; k < 128; k++){
        float cv[4], tv[4];
        #pragma unroll
        for (int ii = 0; ii < 4; ii++){
            int i = i0+ii;
            cv[ii] = (k <= i) ? g_Lp[off(128+i)+128+k] : 0.f;
        }
        #pragma unroll
        for (int jj = 0; jj < 4; jj++) tv[jj] = g_T128[k*128 + j0+jj];
        #pragma unroll
        for (int ii = 0; ii < 4; ii++)
            #pragma unroll
            for (int jj = 0; jj < 4; jj++)
                acc[ii][jj] = fmaf(cv[ii], tv[jj], acc[ii][jj]);
    }
    #pragma unroll
    for (int ii = 0; ii < 4; ii++)
        #pragma unroll
        for (int jj = 0; jj < 4; jj++)
            g_Lp[off(128+i0+ii)+j0+jj] = -acc[ii][jj];
}

// ============ unpack packed Linv -> dense ============
__global__ void unpack_linv_kernel()
{
    int idx = blockIdx.x*blockDim.x + threadIdx.x;
    if (idx >= Mm*Mm) return;
    int i = idx / Mm, j = idx % Mm;
    g_Linv[idx] = (j <= i) ? g_Lp[off(i)+j] : 0.f;
}

// ---------------- masked R from q_sqrt ----------------
__global__ void maskR_kernel(const float* __restrict__ qs)
{
    int idx = blockIdx.x*blockDim.x + threadIdx.x;
    if (idx >= Mm*Mm*Dd) return;
    int a = idx / (Mm*Dd);
    int b = (idx / Dd) % Mm;
    g_R[idx] = (b <= a) ? qs[idx] : 0.f;
}

// ---------------- 64x64 SGEMM ----------------
template<int TA, int TB>
__global__ void sgemm(int M_, int N_, int K_,
                      const float* __restrict__ A, int lda,
                      const float* __restrict__ B, int ldb,
                      float* __restrict__ C, int ldc,
                      float alpha, float beta)
{
    const int BM = 64, BN = 64, BK = 16;
    __shared__ float As[BK][BM+1];
    __shared__ float Bs[BK][BN+1];
    int bm = blockIdx.y*BM, bn = blockIdx.x*BN;
    int tid = threadIdx.x;
    int tm = (tid/16)*4, tn = (tid%16)*4;
    float acc[4][4] = {};
    for (int k0 = 0; k0 < K_; k0 += BK){
        if (!TA){
            for (int i = tid; i < BM*BK; i += 256){
                int kk = i%BK, mm = i/BK;
                int gm = bm+mm, gk = k0+kk;
                As[kk][mm] = (gm < M_ && gk < K_) ? A[(size_t)gm*lda + gk] : 0.f;
            }
        } else {
            for (int i = tid; i < BM*BK; i += 256){
                int mm = i%BM, kk = i/BM;
                int gm = bm+mm, gk = k0+kk;
                As[kk][mm] = (gm < M_ && gk < K_) ? A[(size_t)gk*lda + gm] : 0.f;
            }
        }
        if (!TB){
            for (int i = tid; i < BN*BK; i += 256){
                int nn = i%BN, kk = i/BN;
                int gn = bn+nn, gk = k0+kk;
                Bs[kk][nn] = (gn < N_ && gk < K_) ? B[(size_t)gk*ldb + gn] : 0.f;
            }
        } else {
            for (int i = tid; i < BN*BK; i += 256){
                int kk = i%BK, nn = i/BK;
                int gn = bn+nn, gk = k0+kk;
                Bs[kk][nn] = (gn < N_ && gk < K_) ? B[(size_t)gn*ldb + gk] : 0.f;
            }
        }
        __syncthreads();
        #pragma unroll
        for (int kk = 0; kk < BK; kk++){
            float ra[4], rb[4];
            #pragma unroll
            for (int i = 0; i < 4; i++){ ra[i] = As[kk][tm+i]; rb[i] = Bs[kk][tn+i]; }
            #pragma unroll
            for (int i = 0; i < 4; i++)
                #pragma unroll
                for (int j = 0; j < 4; j++)
                    acc[i][j] = fmaf(ra[i], rb[j], acc[i][j]);
        }
        __syncthreads();
    }
    #pragma unroll
    for (int i = 0; i < 4; i++){
        int gm = bm + tm + i;
        if (gm >= M_) continue;
        #pragma unroll
        for (int j = 0; j < 4; j++){
            int gn = bn + tn + j;
            if (gn >= N_) continue;
            float prev = (beta != 0.f) ? C[(size_t)gm*ldc + gn] : 0.f;
            C[(size_t)gm*ldc + gn] = alpha*acc[i][j] + beta*prev;
        }
    }
}

// ---------------- 128x128 SGEMM, 8x8/thread, split-K, triangular caps ----------------
// CAP=0: none. CAP=1: R*R^T — skip k >= (min(bm,bn)+128)*32 (zero rows of R).
// CAP=2: A1*R — skip k < bn/32 (columns' rows all-zero below).
template<int TA, int TB, int CAP>
__global__ void sgemm128(int M_, int N_, int K_, int Kchunk,
                         const float* __restrict__ A, int lda,
                         const float* __restrict__ B, int ldb,
                         float* __restrict__ C, int ldc, size_t partStride)
{
    const int BM = 128, BN = 128, BK = 16;
    __shared__ float As[BK][BM+4];
    __shared__ float Bs[BK][BN+4];
    int bm = blockIdx.y*BM, bn = blockIdx.x*BN;
    int kbeg = blockIdx.z*Kchunk;
    int kend = kbeg + Kchunk; if (kend > K_) kend = K_;
    if (CAP == 1){
        int cap = ((bm < bn ? bm : bn) + BM)*Dd;
        if (kend > cap) kend = cap;
    }
    if (CAP == 2){
        int kb = (bn >> 5) & ~(BK-1);
        if (kbeg < kb) kbeg = kb;
    }
    float* Cb = C + (size_t)blockIdx.z*partStride;
    int tid = threadIdx.x;
    int tm = (tid/16)*8, tn = (tid%16)*8;
    float acc[8][8] = {};
    for (int k0 = kbeg; k0 < kend; k0 += BK){
        if (!TA){
            #pragma unroll
            for (int i = tid; i < BM*BK; i += 256){
                int kk = i%BK, mm = i/BK;
                As[kk][mm] = A[(size_t)(bm+mm)*lda + (k0+kk)];
            }
        } else {
            #pragma unroll
            for (int i = tid; i < BM*BK; i += 256){
                int mm = i%BM, kk = i/BM;
                As[kk][mm] = A[(size_t)(k0+kk)*lda + (bm+mm)];
            }
        }
        if (!TB){
            #pragma unroll
            for (int i = tid; i < BN*BK; i += 256){
                int nn = i%BN, kk = i/BN;
                Bs[kk][nn] = B[(size_t)(k0+kk)*ldb + (bn+nn)];
            }
        } else {
            #pragma unroll
            for (int i = tid; i < BN*BK; i += 256){
                int kk = i%BK, nn = i/BK;
                Bs[kk][nn] = B[(size_t)(bn+nn)*ldb + (k0+kk)];
            }
        }
        __syncthreads();
        #pragma unroll
        for (int kk = 0; kk < BK; kk++){
            float ra[8], rb[8];
            *(float4*)&ra[0] = *(const float4*)&As[kk][tm];
            *(float4*)&ra[4] = *(const float4*)&As[kk][tm+4];
            *(float4*)&rb[0] = *(const float4*)&Bs[kk][tn];
            *(float4*)&rb[4] = *(const float4*)&Bs[kk][tn+4];
            #pragma unroll
            for (int i = 0; i < 8; i++)
                #pragma unroll
                for (int j = 0; j < 8; j++)
                    acc[i][j] = fmaf(ra[i], rb[j], acc[i][j]);
        }
        __syncthreads();
    }
    #pragma unroll
    for (int i = 0; i < 8; i++){
        float* cp = Cb + (size_t)(bm+tm+i)*ldc + bn + tn;
        *(float4*)cp       = *(float4*)&acc[i][0];
        *(float4*)(cp + 4) = *(float4*)&acc[i][4];
    }
}

// ---------------- sum split-K partials ----------------
__global__ void reduce_parts_kernel(float* __restrict__ out,
                                    const float* __restrict__ parts,
                                    int S, int MN, int addBase)
{
    int idx = blockIdx.x*blockDim.x + threadIdx.x;
    if (idx >= MN) return;
    float s = addBase ? out[idx] : 0.f;
    for (int i = 0; i < S; i++) s += parts[(size_t)i*MN + idx];
    out[idx] = s;
}

// ---------------- batched SYRK for forward_var ----------------
__global__ void var_kernel(float* __restrict__ out_var, const float* __restrict__ beta_p)
{
    __shared__ float T[Mm*Dd];
    int n = blockIdx.x;
    int t = threadIdx.x;
    for (int i = t; i < Mm*Dd; i += 256) T[i] = g_tmpF[(size_t)n*(Mm*Dd) + i];
    __syncthreads();
    float invb = 1.f/beta_p[0];
    int e = t & 31, d0 = (t >> 5)*4;
    float a0=0.f, a1=0.f, a2=0.f, a3=0.f;
    for (int m = 0; m < Mm; m++){
        float te = T[m*32 + e];
        a0 = fmaf(T[m*32 + d0+0], te, a0);
        a1 = fmaf(T[m*32 + d0+1], te, a1);
        a2 = fmaf(T[m*32 + d0+2], te, a2);
        a3 = fmaf(T[m*32 + d0+3], te, a3);
    }
    float* vp = out_var + (size_t)n*Dd*Dd;
    vp[(d0+0)*32 + e] = a0 + ((d0+0)==e ? invb : 0.f);
    vp[(d0+1)*32 + e] = a1 + ((d0+1)==e ? invb : 0.f);
    vp[(d0+2)*32 + e] = a2 + ((d0+2)==e ? invb : 0.f);
    vp[(d0+3)*32 + e] = a3 + ((d0+3)==e ? invb : 0.f);
}

// ---------------- final scalar reduction -> lml ----------------
__global__ void reduce_lml_kernel(float* __restrict__ out_lml,
                                  const float* __restrict__ var_p,
                                  const float* __restrict__ beta_p,
                                  const float* __restrict__ qs)
{
    __shared__ double red[256];
    int t = threadIdx.x;
    double a1=0, a2=0, a3=0, a4=0, a5=0, a6=0;
    for (int i = t; i < Mm*Mm; i += 256){
        double kv = g_Kinv[i], uu = g_uuT[i];
        a1 += kv*(double)g_psi2[i];
        a2 += kv*uu;
        a3 += (double)g_KPK[i]*uu;
        a4 += (double)g_G[i]*uu;
    }
    for (int i = t; i < Mm; i += 256) a5 += log((double)g_Ldiag[i]);
    for (int i = t; i < Mm*Dd; i += 256){
        int mm = i/Dd, dd = i%Dd;
        double x = (double)qs[(size_t)mm*Mm*Dd + (size_t)mm*Dd + dd];
        a6 += log(x*x);
    }
    double sums[6] = {a1,a2,a3,a4,a5,a6};
    double res[6];
    for (int s = 0; s < 6; s++){
        red[t] = sums[s];
        __syncthreads();
        for (int w = 128; w > 0; w >>= 1){
            if (t < w) red[t] += red[t+w];
            __syncthreads();
        }
        res[s] = red[0];
        __syncthreads();
    }
    if (t == 0){
        double variance = var_p[0], beta = beta_p[0];
        double psi0 = (double)Nn*variance;
        double lml = -0.5*beta*(double)Dd*(psi0 - res[0]);
        double logdetK = 2.0*res[4];
        double kl = 0.5*(res[1] - (double)(Mm*Dd) + (double)Dd*logdetK - res[5]);
        lml -= kl;
        lml -= 0.5*beta*(res[2] - res[3]);
        out_lml[0] = (float)lml;
    }
}

// ---------------- host launcher with fork/join stream overlap ----------------
extern "C" void kernel_launch(void* const* d_in, const int* in_sizes, int n_in,
                              void* d_out, int out_size)
{
    const float* Xmean = (const float*)d_in[0];
    const float* Xvar  = (const float*)d_in[1];
    const float* Z     = (const float*)d_in[2];
    const float* qmu   = (const float*)d_in[3];
    const float* qs    = (const float*)d_in[4];
    const float* ls    = (const float*)d_in[5];
    const float* var_p = (const float*)d_in[6];
    const float* beta_p= (const float*)d_in[7];

    float* out      = (float*)d_out;
    float* out_mean = out;
    float* out_var  = out + Nn*Dd;
    float* out_lml  = out + Nn*Dd + (size_t)Nn*Dd*Dd;

    float *pPsi1, *pKinv, *pA1, *pR, *puuT, *puuTp, *pGp, *pP2, *pKPK, *pG, *pTmpF, *pPsi2, *pLinv;
    cudaGetSymbolAddress((void**)&pPsi1, g_psi1);
    cudaGetSymbolAddress((void**)&pKinv, g_Kinv);
    cudaGetSymbolAddress((void**)&pA1,   g_A1);
    cudaGetSymbolAddress((void**)&pR,    g_R);
    cudaGetSymbolAddress((void**)&puuT,  g_uuT);
    cudaGetSymbolAddress((void**)&puuTp, g_uuTp);
    cudaGetSymbolAddress((void**)&pGp,   g_Gp);
    cudaGetSymbolAddress((void**)&pP2,   g_P2);
    cudaGetSymbolAddress((void**)&pKPK,  g_KPK);
    cudaGetSymbolAddress((void**)&pG,    g_G);
    cudaGetSymbolAddress((void**)&pTmpF, g_tmpF);
    cudaGetSymbolAddress((void**)&pPsi2, g_psi2);
    cudaGetSymbolAddress((void**)&pLinv, g_Linv);

    const int CHOLINV_SMEM = (TRI + 8448)*4;   // 165376 B
    cudaFuncSetAttribute(cholinv_kernel, cudaFuncAttributeMaxDynamicSharedMemorySize, CHOLINV_SMEM);

    static cudaStream_t s1 = nullptr, s2 = nullptr;
    static cudaEvent_t e0 = nullptr, e1 = nullptr, e2 = nullptr, e3 = nullptr, e4 = nullptr;
    if (!s1){
        cudaStreamCreateWithFlags(&s1, cudaStreamNonBlocking);
        cudaStreamCreateWithFlags(&s2, cudaStreamNonBlocking);
        cudaEventCreateWithFlags(&e0, cudaEventDisableTiming);
        cudaEventCreateWithFlags(&e1, cudaEventDisableTiming);
        cudaEventCreateWithFlags(&e2, cudaEventDisableTiming);
        cudaEventCreateWithFlags(&e3, cudaEventDisableTiming);
        cudaEventCreateWithFlags(&e4, cudaEventDisableTiming);
    }

    // ---- common prep ----
    prep_n_kernel<<<(Nn+255)/256, 256>>>(Xmean, Xvar, ls);
    prep_kmm_kernel<<<(Mm*Mm+255)/256, 256>>>(Z, ls, var_p);
    cudaEventRecord(e0, 0);

    // ---- branch s1: Cholesky + block inversion chain ----
    cudaStreamWaitEvent(s1, e0, 0);
    cholinv_kernel<<<1, 1024, CHOLINV_SMEM, s1>>>();
    inv_lvl2_kernel<<<2, 256, 0, s1>>>();
    inv_lvl3a_kernel<<<4, 256, 0, s1>>>();
    inv_lvl3b_kernel<<<4, 256, 0, s1>>>();
    unpack_linv_kernel<<<(Mm*Mm+255)/256, 256, 0, s1>>>();
    {
        dim3 g((Mm+63)/64, (Mm+63)/64);
        sgemm<1,0><<<g, 256, 0, s1>>>(Mm, Mm, Mm, pLinv, Mm, pLinv, Mm, pKinv, Mm, 1.f, 0.f);
    }
    cudaEventRecord(e1, s1);

    // ---- branch s2: R / uuT chain ----
    cudaStreamWaitEvent(s2, e0, 0);
    maskR_kernel<<<(Mm*Mm*Dd+255)/256, 256, 0, s2>>>(qs);
    {
        dim3 g((Mm+63)/64, (Mm+63)/64);
        sgemm<0,1><<<g, 256, 0, s2>>>(Mm, Mm, Dd, qmu, Dd, qmu, Dd, puuT, Mm, 1.f, 0.f);
        dim3 g2(Mm/128, Mm/128, 16);
        sgemm128<0,1,1><<<g2, 256, 0, s2>>>(Mm, Mm, Mm*Dd, (Mm*Dd)/16, pR, Mm*Dd, pR, Mm*Dd,
                                            puuTp, Mm, (size_t)Mm*Mm);
        reduce_parts_kernel<<<(Mm*Mm+255)/256, 256, 0, s2>>>(puuT, puuTp, 16, Mm*Mm, 1);
    }
    cudaEventRecord(e2, s2);

    // ---- origin stream: psi chain ----
    {
        dim3 b(32,8), g(Mm/32, Nn/8);
        e2_kernel<<<g, b>>>(Z);
        psi1_kernel<<<g, b>>>(Z, var_p);
    }
    {
        dim3 b(16,16), g(136, 8);
        psi2_kernel<<<g, b>>>(Z);
        psi2_combine_kernel<<<(Mm*Mm+255)/256, 256>>>(var_p);
    }

    // ---- join Kinv, compute A1 ----
    cudaStreamWaitEvent(0, e1, 0);
    {
        dim3 g((Mm+63)/64, (Nn+63)/64);
        sgemm<0,0><<<g, 256>>>(Nn, Mm, Mm, pPsi1, Mm, pKinv, Mm, pA1, Mm, 1.f, 0.f);
    }
    cudaEventRecord(e3, 0);

    // ---- branch s1 (post-A1): mean, P2, KPK, G ----
    cudaStreamWaitEvent(s1, e3, 0);
    {
        dim3 g((Dd+63)/64, (Nn+63)/64);
        sgemm<0,0><<<g, 256, 0, s1>>>(Nn, Dd, Mm, pA1, Mm, qmu, Dd, out_mean, Dd, 1.f, 0.f);
    }
    {
        dim3 g((Mm+63)/64, (Mm+63)/64);
        sgemm<0,0><<<g, 256, 0, s1>>>(Mm, Mm, Mm, pKinv, Mm, pPsi2, Mm, pP2, Mm, 1.f, 0.f);
        sgemm<0,0><<<g, 256, 0, s1>>>(Mm, Mm, Mm, pP2, Mm, pKinv, Mm, pKPK, Mm, 1.f, 0.f);
    }
    {
        dim3 g(Mm/128, Mm/128, 8);
        sgemm128<1,0,0><<<g, 256, 0, s1>>>(Mm, Mm, Nn, Nn/8, pA1, Mm, pA1, Mm,
                                           pGp, Mm, (size_t)Mm*Mm);
        reduce_parts_kernel<<<(Mm*Mm+255)/256, 256, 0, s1>>>(pG, pGp, 8, Mm*Mm, 0);
    }
    cudaEventRecord(e4, s1);

    // ---- origin stream: tmpF -> var ----
    cudaStreamWaitEvent(0, e2, 0);
    {
        dim3 g((Mm*Dd)/128, Nn/128, 1);
        sgemm128<0,0,2><<<g, 256>>>(Nn, Mm*Dd, Mm, Mm, pA1, Mm, pR, Mm*Dd,
                                    pTmpF, Mm*Dd, 0);
    }
    var_kernel<<<Nn, 256>>>(out_var, beta_p);

    // ---- final join and lml ----
    cudaStreamWaitEvent(0, e4, 0);
    reduce_lml_kernel<<<1, 256>>>(out_lml, var_p, beta_p, qs);
}